// round 1
// baseline (speedup 1.0000x reference)
#include <cuda_runtime.h>
#include <math.h>

// ---------------- problem constants ----------------
#define CC      256
#define NHH     8
#define DHH     32
#define LQQ     5376
#define BTT     4
#define NLAYERS 6
#define DFFD    1024
#define H4D     128
#define NPIX    (H4D*H4D)          // 16384
#define KCONV   (CC*9)             // 2304

// ---------------- scratch (device globals; no cudaMalloc allowed) -------
__device__ float g_posf[BTT*LQQ*CC];
__device__ float g_q   [BTT*LQQ*CC];
__device__ float g_v   [BTT*LQQ*CC];
__device__ float g_off [BTT*LQQ*NHH*12*2];
__device__ float g_aw  [BTT*LQQ*NHH*12];
__device__ float g_acc [BTT*LQQ*CC];
__device__ float g_tmp [BTT*LQQ*CC];
__device__ float g_ff  [BTT*LQQ*DFFD];
__device__ float g_x   [BTT*CC*NPIX];
__device__ float g_wt  [KCONV*CC];

// ---------------- helpers ----------------
__device__ __forceinline__ void qlevel(int q, int& H, int& qq) {
    if (q < 256)       { H = 16; qq = q; }
    else if (q < 1280) { H = 32; qq = q - 256; }
    else               { H = 64; qq = q - 1280; }
}

// ---------------- token build: output0 and posf ----------------
__global__ __launch_bounds__(256) void k_build(
    const float* __restrict__ s0, const float* __restrict__ s1, const float* __restrict__ s2,
    const float* __restrict__ p0, const float* __restrict__ p1, const float* __restrict__ p2,
    const float* __restrict__ lev, float* __restrict__ out, float* __restrict__ posf)
{
    long long i = (long long)blockIdx.x * 256 + threadIdx.x;   // BTT*LQQ*CC total
    int c = (int)(i % CC);
    long long r = i / CC;
    int q  = (int)(r % LQQ);
    int bt = (int)(r / LQQ);
    int l, H, qq;
    if (q < 256)       { l = 0; H = 16; qq = q; }
    else if (q < 1280) { l = 1; H = 32; qq = q - 256; }
    else               { l = 2; H = 64; qq = q - 1280; }
    const float* s = (l == 0) ? s0 : (l == 1 ? s1 : s2);
    const float* p = (l == 0) ? p0 : (l == 1 ? p1 : p2);
    long long src = ((long long)(bt * CC + c)) * H * H + qq;
    out[i]  = s[src];
    posf[i] = p[src] + lev[l * CC + c];
}

__global__ __launch_bounds__(256) void k_copy(const float* __restrict__ a, float* __restrict__ b)
{
    long long i = (long long)blockIdx.x * 256 + threadIdx.x;
    b[i] = a[i];
}

__global__ __launch_bounds__(256) void k_addq(const float* __restrict__ a, const float* __restrict__ b,
                                              float* __restrict__ c)
{
    long long i = (long long)blockIdx.x * 256 + threadIdx.x;
    c[i] = a[i] + b[i];
}

// ---------------- generic tiled fp32 GEMM: C = A(MxK) * B(KxN) + bias ----------------
// BM=BN=64, BK=16, 256 threads, 4x4 acc per thread.
// Requires M%64==0, K%16==0, lda/ldb/ldc %4==0. N may be ragged (guarded).
template<bool RELU, bool BIASROW, bool MASKB>
__global__ __launch_bounds__(256) void k_gemm(
    const float* __restrict__ A, const float* __restrict__ B,
    const float* __restrict__ bias, float* __restrict__ Cm,
    int M, int N, int K, int lda, int ldb, int ldc,
    long long azs, long long bzs, long long czs)
{
    A  += (long long)blockIdx.z * azs;
    if (MASKB) {
        // B is mask_features (Bb,C,T,H,W): z = bt = b*T+t
        long long boff = ((long long)((blockIdx.z >> 1) * (CC * 2) + (blockIdx.z & 1))) * NPIX;
        B += boff;
    } else {
        B += (long long)blockIdx.z * bzs;
    }
    Cm += (long long)blockIdx.z * czs;

    __shared__ float As[16][64];
    __shared__ float Bs[16][64];

    int tid = threadIdx.x;
    int tx = tid & 15, ty = tid >> 4;
    int m0 = blockIdx.y * 64, n0 = blockIdx.x * 64;

    float acc[4][4];
#pragma unroll
    for (int i = 0; i < 4; i++)
#pragma unroll
        for (int j = 0; j < 4; j++) acc[i][j] = 0.f;

    for (int k0 = 0; k0 < K; k0 += 16) {
        {   // A tile: 64 rows x 16 k, float4 along K
            int r = tid >> 2, k4 = (tid & 3) * 4;
            float4 v = *(const float4*)&A[(long long)(m0 + r) * lda + k0 + k4];
            As[k4 + 0][r] = v.x; As[k4 + 1][r] = v.y;
            As[k4 + 2][r] = v.z; As[k4 + 3][r] = v.w;
        }
        {   // B tile: 16 k-rows x 64 cols
            int kr = tid >> 4, n4 = (tid & 15) * 4;
            const float* bp = &B[(long long)(k0 + kr) * ldb + n0 + n4];
            float4 v;
            if (n0 + 64 <= N) {
                v = *(const float4*)bp;
            } else {
                v.x = (n0 + n4 + 0 < N) ? bp[0] : 0.f;
                v.y = (n0 + n4 + 1 < N) ? bp[1] : 0.f;
                v.z = (n0 + n4 + 2 < N) ? bp[2] : 0.f;
                v.w = (n0 + n4 + 3 < N) ? bp[3] : 0.f;
            }
            *(float4*)&Bs[kr][n4] = v;
        }
        __syncthreads();
#pragma unroll
        for (int k = 0; k < 16; k++) {
            float4 av = *(const float4*)&As[k][ty * 4];
            float4 bv = *(const float4*)&Bs[k][tx * 4];
            float a_[4] = {av.x, av.y, av.z, av.w};
            float b_[4] = {bv.x, bv.y, bv.z, bv.w};
#pragma unroll
            for (int ii = 0; ii < 4; ii++)
#pragma unroll
                for (int jj = 0; jj < 4; jj++)
                    acc[ii][jj] += a_[ii] * b_[jj];
        }
        __syncthreads();
    }

#pragma unroll
    for (int i = 0; i < 4; i++) {
        int m = m0 + ty * 4 + i;
#pragma unroll
        for (int j = 0; j < 4; j++) {
            int n = n0 + tx * 4 + j;
            if (n < N) {
                float v = acc[i][j] + (BIASROW ? bias[m] : bias[n]);
                if (RELU) v = v > 0.f ? v : 0.f;
                Cm[(long long)m * ldc + n] = v;
            }
        }
    }
}

// ---------------- deformable sampling: one warp per (bt,q,head) ----------------
__global__ __launch_bounds__(256) void k_sample(
    const float* __restrict__ v, const float* __restrict__ off,
    const float* __restrict__ aw, float* __restrict__ acc)
{
    int bq   = blockIdx.x;              // bt*LQQ + q
    int h    = threadIdx.x >> 5;        // 8 warps = 8 heads
    int lane = threadIdx.x & 31;        // head-dim
    int bt = bq / LQQ, q = bq % LQQ;

    int Hq, qq;
    qlevel(q, Hq, qq);
    float rx = ((qq % Hq) + 0.5f) / (float)Hq;
    float ry = ((qq / Hq) + 0.5f) / (float)Hq;

    const float* awp = aw + ((long long)bq * NHH + h) * 12;
    float a[12];
    float m = -1e30f;
#pragma unroll
    for (int j = 0; j < 12; j++) { a[j] = awp[j]; m = fmaxf(m, a[j]); }
    float s = 0.f;
#pragma unroll
    for (int j = 0; j < 12; j++) { a[j] = __expf(a[j] - m); s += a[j]; }
    float inv = 1.f / s;

    const float* offp = off + ((long long)bq * NHH + h) * 24;
    float sum = 0.f;
    const int starts[3] = {0, 256, 1280};
    const int hs[3]     = {16, 32, 64};

#pragma unroll
    for (int l = 0; l < 3; l++) {
        int H = hs[l], W = hs[l];
        const float* vl = v + ((long long)bt * LQQ + starts[l]) * CC + h * DHH + lane;
#pragma unroll
        for (int p = 0; p < 4; p++) {
            float ox = offp[(l * 4 + p) * 2 + 0];
            float oy = offp[(l * 4 + p) * 2 + 1];
            float x = rx * W + ox - 0.5f;
            float y = ry * H + oy - 0.5f;
            float x0f = floorf(x), y0f = floorf(y);
            int x0 = (int)x0f, y0 = (int)y0f;
            float fx = x - x0f, fy = y - y0f;
            float w00 = (1.f - fx) * (1.f - fy);
            float w01 = fx * (1.f - fy);
            float w10 = (1.f - fx) * fy;
            float w11 = fx * fy;
            float g = 0.f;
            if (y0 >= 0 && y0 < H) {
                if (x0 >= 0 && x0 < W)         g += w00 * vl[(long long)(y0 * W + x0) * CC];
                if (x0 + 1 >= 0 && x0 + 1 < W) g += w01 * vl[(long long)(y0 * W + x0 + 1) * CC];
            }
            if (y0 + 1 >= 0 && y0 + 1 < H) {
                if (x0 >= 0 && x0 < W)         g += w10 * vl[(long long)((y0 + 1) * W + x0) * CC];
                if (x0 + 1 >= 0 && x0 + 1 < W) g += w11 * vl[(long long)((y0 + 1) * W + x0 + 1) * CC];
            }
            sum += (a[l * 4 + p] * inv) * g;
        }
    }
    acc[(long long)bq * CC + h * DHH + lane] = sum;
}

// ---------------- layernorm: y = LN(res + delta)*g + b, one block per row ----------------
__global__ __launch_bounds__(256) void k_ln(
    const float* __restrict__ res, const float* __restrict__ delta,
    const float* __restrict__ g, const float* __restrict__ b,
    float* __restrict__ out)
{
    int row = blockIdx.x, c = threadIdx.x;
    long long idx = (long long)row * CC + c;
    float x = res[idx] + delta[idx];
    float s1 = x, s2 = x * x;
#pragma unroll
    for (int o = 16; o; o >>= 1) {
        s1 += __shfl_xor_sync(0xffffffffu, s1, o);
        s2 += __shfl_xor_sync(0xffffffffu, s2, o);
    }
    __shared__ float a1[8], a2[8];
    int wid = c >> 5, ln = c & 31;
    if (ln == 0) { a1[wid] = s1; a2[wid] = s2; }
    __syncthreads();
    float S1 = 0.f, S2 = 0.f;
#pragma unroll
    for (int k = 0; k < 8; k++) { S1 += a1[k]; S2 += a2[k]; }
    float mean = S1 * (1.f / 256.f);
    float var  = S2 * (1.f / 256.f) - mean * mean;
    float r = rsqrtf(var + 1e-5f);
    out[idx] = (x - mean) * r * g[c] + b[c];
}

// ---------------- bilinear upsample(64->128) of finest tokens, add into x ----------------
__global__ __launch_bounds__(256) void k_upadd(const float* __restrict__ outp, float* __restrict__ x)
{
    long long i = (long long)blockIdx.x * 256 + threadIdx.x;  // BTT*CC*NPIX
    int w  = (int)(i & 127);
    int h  = (int)((i >> 7) & 127);
    int c  = (int)((i >> 14) & 255);
    int bt = (int)(i >> 22);
    float sx = fminf(fmaxf(w * 0.5f - 0.25f, 0.f), 63.f);
    float sy = fminf(fmaxf(h * 0.5f - 0.25f, 0.f), 63.f);
    int x0 = (int)sx, y0 = (int)sy;
    int x1 = min(x0 + 1, 63), y1 = min(y0 + 1, 63);
    float fx = sx - x0, fy = sy - y0;
    const float* base = outp + ((long long)bt * LQQ + 1280) * CC + c;
    float v00 = base[(long long)(y0 * 64 + x0) * CC];
    float v01 = base[(long long)(y0 * 64 + x1) * CC];
    float v10 = base[(long long)(y1 * 64 + x0) * CC];
    float v11 = base[(long long)(y1 * 64 + x1) * CC];
    x[i] += v00 * (1.f - fx) * (1.f - fy) + v01 * fx * (1.f - fy)
          + v10 * (1.f - fx) * fy + v11 * fx * fy;
}

// ---------------- conv weight transpose: Wt[kk][oc] = W[oc][kk] ----------------
__global__ __launch_bounds__(256) void k_wt(const float* __restrict__ w, float* __restrict__ wt)
{
    int i = blockIdx.x * 256 + threadIdx.x;     // KCONV*CC
    int c  = i & 255;
    int kk = i >> 8;
    wt[i] = w[(long long)c * KCONV + kk];
}

// ---------------- 3x3 conv (pad 1) as implicit GEMM; mask += relu(conv + bias) ----------------
__global__ __launch_bounds__(256) void k_conv(
    const float* __restrict__ x, const float* __restrict__ wt,
    const float* __restrict__ bias, float* __restrict__ mask)
{
    __shared__ float As[16][64];   // [k][pixel]
    __shared__ float Bs[16][64];   // [k][oc]

    int tid = threadIdx.x;
    int tx = tid & 15, ty = tid >> 4;
    int p0  = blockIdx.x * 64;     // 64 consecutive pixels (same bt, same h)
    int oc0 = blockIdx.y * 64;
    int bt = p0 >> 14;
    int hw = p0 & 16383;
    int h  = hw >> 7;
    int w0 = hw & 127;

    float acc[4][4];
#pragma unroll
    for (int i = 0; i < 4; i++)
#pragma unroll
        for (int j = 0; j < 4; j++) acc[i][j] = 0.f;

    for (int k0 = 0; k0 < KCONV; k0 += 16) {
        {
            int kr = tid >> 4;          // 0..15
            int pc = (tid & 15) * 4;    // 0..60
            int kk = k0 + kr;
            int ci = kk / 9;
            int r  = kk - ci * 9;
            int dy = r / 3 - 1;
            int dx = r - (r / 3) * 3 - 1;
            int h2 = h + dy;
            bool hok = (h2 >= 0) && (h2 < H4D);
            const float* xp = x + (((long long)bt * CC + ci) * H4D + h2) * H4D;
#pragma unroll
            for (int j = 0; j < 4; j++) {
                int w2 = w0 + pc + j + dx;
                As[kr][pc + j] = (hok && w2 >= 0 && w2 < H4D) ? xp[w2] : 0.f;
            }
        }
        {
            int kr = tid >> 4, n4 = (tid & 15) * 4;
            *(float4*)&Bs[kr][n4] = *(const float4*)&wt[(long long)(k0 + kr) * CC + oc0 + n4];
        }
        __syncthreads();
#pragma unroll
        for (int k = 0; k < 16; k++) {
            float4 av = *(const float4*)&As[k][ty * 4];
            float4 bv = *(const float4*)&Bs[k][tx * 4];
            float a_[4] = {av.x, av.y, av.z, av.w};
            float b_[4] = {bv.x, bv.y, bv.z, bv.w};
#pragma unroll
            for (int ii = 0; ii < 4; ii++)
#pragma unroll
                for (int jj = 0; jj < 4; jj++)
                    acc[ii][jj] += a_[ii] * b_[jj];
        }
        __syncthreads();
    }

    int b_ = bt >> 1, t_ = bt & 1;
#pragma unroll
    for (int i = 0; i < 4; i++) {
        int w = w0 + ty * 4 + i;
#pragma unroll
        for (int j = 0; j < 4; j++) {
            int oc = oc0 + tx * 4 + j;
            float v = acc[i][j] + bias[oc];
            v = v > 0.f ? v : 0.f;
            long long mi = (((long long)(b_ * CC + oc) * 2 + t_)) * NPIX + (long long)h * H4D + w;
            mask[mi] += v;
        }
    }
}

// ---------------- host launcher ----------------
extern "C" void kernel_launch(void* const* d_in, const int* in_sizes, int n_in,
                              void* d_out, int out_size)
{
    const float *src0, *src1, *src2, *pos0, *pos1, *pos2;
    if (in_sizes[1] == in_sizes[0]) {
        // setup_inputs dict order: src0,pos0,src1,pos1,src2,pos2
        src0 = (const float*)d_in[0]; pos0 = (const float*)d_in[1];
        src1 = (const float*)d_in[2]; pos1 = (const float*)d_in[3];
        src2 = (const float*)d_in[4]; pos2 = (const float*)d_in[5];
    } else {
        // signature order: src0,src1,src2,pos0,pos1,pos2
        src0 = (const float*)d_in[0]; src1 = (const float*)d_in[1]; src2 = (const float*)d_in[2];
        pos0 = (const float*)d_in[3]; pos1 = (const float*)d_in[4]; pos2 = (const float*)d_in[5];
    }
    const float* mf     = (const float*)d_in[6];
    const float* lev    = (const float*)d_in[7];
    const float* off_w  = (const float*)d_in[8];
    const float* off_b  = (const float*)d_in[9];
    const float* aw_w   = (const float*)d_in[10];
    const float* aw_b   = (const float*)d_in[11];
    const float* val_w  = (const float*)d_in[12];
    const float* val_b  = (const float*)d_in[13];
    const float* out_w  = (const float*)d_in[14];
    const float* out_b  = (const float*)d_in[15];
    const float* ln1_g  = (const float*)d_in[16];
    const float* ln1_b  = (const float*)d_in[17];
    const float* ff1_w  = (const float*)d_in[18];
    const float* ff1_b  = (const float*)d_in[19];
    const float* ff2_w  = (const float*)d_in[20];
    const float* ff2_b  = (const float*)d_in[21];
    const float* ln2_g  = (const float*)d_in[22];
    const float* ln2_b  = (const float*)d_in[23];
    const float* lat_w  = (const float*)d_in[24];
    const float* lat_b  = (const float*)d_in[25];
    const float* outc_w = (const float*)d_in[26];
    const float* outc_b = (const float*)d_in[27];

    float* outp = (float*)d_out;                       // (BT,LQ,C)
    float* mask = outp + (size_t)BTT * LQQ * CC;       // (B,C,T,H4,W4)

    float *posf, *qb, *vb, *offb, *awb, *accb, *tmpb, *ffb, *xb, *wtb;
    cudaGetSymbolAddress((void**)&posf, g_posf);
    cudaGetSymbolAddress((void**)&qb,   g_q);
    cudaGetSymbolAddress((void**)&vb,   g_v);
    cudaGetSymbolAddress((void**)&offb, g_off);
    cudaGetSymbolAddress((void**)&awb,  g_aw);
    cudaGetSymbolAddress((void**)&accb, g_acc);
    cudaGetSymbolAddress((void**)&tmpb, g_tmp);
    cudaGetSymbolAddress((void**)&ffb,  g_ff);
    cudaGetSymbolAddress((void**)&xb,   g_x);
    cudaGetSymbolAddress((void**)&wtb,  g_wt);

    const int ROWS = BTT * LQQ;          // 21504
    const int TOKB = ROWS;               // blocks for 256-thread elementwise over tokens*C/256

    k_build<<<TOKB, 256>>>(src0, src1, src2, pos0, pos1, pos2, lev, outp, posf);
    k_copy<<<(BTT * CC * NPIX) / 256, 256>>>(mf, mask);

    dim3 blk(256);
    for (int i = 0; i < NLAYERS; i++) {
        k_addq<<<TOKB, 256>>>(outp, posf, qb);

        // v = output @ val_w + val_b
        k_gemm<false, false, false><<<dim3(4, ROWS / 64, 1), blk>>>(
            outp, val_w + (long long)i * 65536, val_b + i * 256, vb,
            ROWS, 256, 256, 256, 256, 256, 0, 0, 0);
        // off = q @ off_w + off_b
        k_gemm<false, false, false><<<dim3(3, ROWS / 64, 1), blk>>>(
            qb, off_w + (long long)i * 256 * 192, off_b + i * 192, offb,
            ROWS, 192, 256, 256, 192, 192, 0, 0, 0);
        // aw_raw = q @ aw_w + aw_b (softmax fused into sampler)
        k_gemm<false, false, false><<<dim3(2, ROWS / 64, 1), blk>>>(
            qb, aw_w + (long long)i * 256 * 96, aw_b + i * 96, awb,
            ROWS, 96, 256, 256, 96, 96, 0, 0, 0);

        k_sample<<<ROWS, 256>>>(vb, offb, awb, accb);

        // attn = acc @ out_w + out_b
        k_gemm<false, false, false><<<dim3(4, ROWS / 64, 1), blk>>>(
            accb, out_w + (long long)i * 65536, out_b + i * 256, tmpb,
            ROWS, 256, 256, 256, 256, 256, 0, 0, 0);
        k_ln<<<ROWS, 256>>>(outp, tmpb, ln1_g + i * 256, ln1_b + i * 256, outp);

        // ff = relu(out @ ff1 + b1) @ ff2 + b2
        k_gemm<true, false, false><<<dim3(16, ROWS / 64, 1), blk>>>(
            outp, ff1_w + (long long)i * 256 * 1024, ff1_b + i * 1024, ffb,
            ROWS, 1024, 256, 256, 1024, 1024, 0, 0, 0);
        k_gemm<false, false, false><<<dim3(4, ROWS / 64, 1), blk>>>(
            ffb, ff2_w + (long long)i * 1024 * 256, ff2_b + i * 256, tmpb,
            ROWS, 256, 1024, 1024, 256, 256, 0, 0, 0);
        k_ln<<<ROWS, 256>>>(outp, tmpb, ln2_g + i * 256, ln2_b + i * 256, outp);

        // FPN: x = lat1x1(mask) + bias (per-channel row bias), z = bt
        k_gemm<false, true, true><<<dim3(NPIX / 64, 4, 4), blk>>>(
            lat_w + (long long)i * 65536, mask, lat_b + i * 256, xb,
            256, NPIX, 256, 256, 2 * NPIX, NPIX,
            0, 0, (long long)CC * NPIX);
        // x += bilinear_upsample(finest tokens)
        k_upadd<<<(BTT * CC * NPIX) / 256, 256>>>(outp, xb);
        // transpose conv weights for implicit GEMM
        k_wt<<<KCONV * CC / 256, 256>>>(outc_w + (long long)i * CC * KCONV, wtb);
        // mask += relu(conv3x3(x) + b)
        k_conv<<<dim3((BTT * NPIX) / 64, 4), blk>>>(xb, wtb, outc_b + i * 256, mask);
    }
}

// round 3
// speedup vs baseline: 2.1676x; 2.1676x over previous
#include <cuda_runtime.h>
#include <cstdint>
#include <math.h>

// ---------------- problem constants ----------------
#define CC        256
#define LQQ       5376
#define BTT       4
#define NLAYERS   6
#define NPIX      16384
#define ROWS_TOK  (BTT*LQQ)     // 21504 = 168*128
#define ROWS_PIX  (BTT*NPIX)    // 65536 = 512*128
#define KCONV     2304

// ---------------- scratch (device globals) ----------------
__device__ float g_posf[ROWS_TOK*CC];
__device__ float g_q   [ROWS_TOK*CC];
__device__ float g_v   [ROWS_TOK*CC];
__device__ float g_off [ROWS_TOK*256];
__device__ float g_aw  [ROWS_TOK*128];
__device__ float g_acc [ROWS_TOK*CC];
__device__ float g_tmp [ROWS_TOK*CC];
__device__ float g_ff  [ROWS_TOK*1024];
__device__ float g_xtok[ (long long)ROWS_PIX*CC ];
__device__ float g_mtok[ (long long)ROWS_PIX*CC ];
__device__ float g_valT[NLAYERS*65536];
__device__ float g_offT[NLAYERS*65536];
__device__ float g_awT [NLAYERS*32768];
__device__ float g_outT[NLAYERS*65536];
__device__ float g_ff1T[NLAYERS*262144];
__device__ float g_ff2T[NLAYERS*262144];
__device__ float g_cvT [NLAYERS*589824];
__device__ float g_offb[NLAYERS*256];
__device__ float g_awb [NLAYERS*128];

// ---------------- tf32 helpers ----------------
__device__ __forceinline__ uint32_t tf32u(float x){
    uint32_t u; asm("cvt.rna.tf32.f32 %0, %1;" : "=r"(u) : "f"(x)); return u;
}
__device__ __forceinline__ void mma_tf32(float* d, const uint32_t* a, const uint32_t* b){
    asm volatile("mma.sync.aligned.m16n8k8.row.col.f32.tf32.tf32.f32 "
        "{%0,%1,%2,%3}, {%4,%5,%6,%7}, {%8,%9}, {%0,%1,%2,%3};"
        : "+f"(d[0]), "+f"(d[1]), "+f"(d[2]), "+f"(d[3])
        : "r"(a[0]), "r"(a[1]), "r"(a[2]), "r"(a[3]), "r"(b[0]), "r"(b[1]));
}

// ---------------- tf32 mma GEMM: C[M,N] = A[M,K] * B^T (B is NxK K-major) + bias ----------------
// AMODE 0: A row-major (lda). AMODE 1: conv3x3 gather from x_tok (bt,128,128,256), K=2304.
// EPI 0: C = acc+bias; EPI 1: relu(acc+bias); EPI 2: C += relu(acc+bias).
// BM=BN=128, BK=32, 256 threads (8 warps, 4x2), warp tile 32x64.
#define LDS_ROW 36
#define SMEM_MMA (4 * 4608 * 4)   // A0,A1,B0,B1 each 128*36 floats

template<int AMODE>
__device__ __forceinline__ float4 load_a(const float* __restrict__ A, long long row, int kc, int kslot, int lda)
{
    if (AMODE == 0) {
        return *(const float4*)(A + row * (long long)lda + (kc << 5) + kslot * 4);
    } else {
        int bt = (int)(row >> 14);
        int p  = (int)(row & 16383);
        int hh = p >> 7, ww = p & 127;
        int r3 = kc >> 3;
        int q3 = r3 / 3;
        int dy = q3 - 1, dx = r3 - q3 * 3 - 1;
        int h2 = hh + dy, w2 = ww + dx;
        if ((unsigned)h2 < 128u && (unsigned)w2 < 128u)
            return *(const float4*)(A + ((((long long)bt << 7) + h2) * 128 + w2) * 256
                                      + ((kc & 7) << 5) + kslot * 4);
        return make_float4(0.f, 0.f, 0.f, 0.f);
    }
}

__device__ __forceinline__ void st_cvt(float* dst, float4 v){
    uint4 u;
    u.x = tf32u(v.x); u.y = tf32u(v.y); u.z = tf32u(v.z); u.w = tf32u(v.w);
    *(uint4*)dst = u;
}

template<int AMODE, int EPI>
__global__ __launch_bounds__(256) void k_mma(
    const float* __restrict__ A, const float* __restrict__ B,
    const float* __restrict__ bias, float* __restrict__ C,
    int K, int lda, int ldb, int ldc)
{
    extern __shared__ float sm[];
    float* const AsB[2] = { sm,        sm + 4608 };
    float* const BsB[2] = { sm + 9216, sm + 13824 };

    const int tid  = threadIdx.x;
    const int lane = tid & 31;
    const int wid  = tid >> 5;
    const int wm   = wid >> 1;          // 0..3
    const int wn   = wid & 1;           // 0..1
    const long long m0 = (long long)blockIdx.y * 128;
    const int n0 = blockIdx.x * 128;

    const int kslot = tid & 7;          // float4 slot in 32-wide K chunk
    const int mrow  = tid >> 3;         // 0..31

    float acc[2][8][4];
#pragma unroll
    for (int i = 0; i < 2; i++)
#pragma unroll
        for (int j = 0; j < 8; j++)
#pragma unroll
            for (int t = 0; t < 4; t++) acc[i][j][t] = 0.f;

    const int NC = K >> 5;

    // prologue: tile 0 into buffer 0
    {
#pragma unroll
        for (int r = 0; r < 4; r++) {
            float4 va = load_a<AMODE>(A, m0 + mrow + r * 32, 0, kslot, lda);
            float4 vb = *(const float4*)(B + (long long)(n0 + mrow + r * 32) * ldb + kslot * 4);
            st_cvt(&AsB[0][(mrow + r * 32) * LDS_ROW + kslot * 4], va);
            st_cvt(&BsB[0][(mrow + r * 32) * LDS_ROW + kslot * 4], vb);
        }
    }
    __syncthreads();

    for (int kc = 0; kc < NC; kc++) {
        const bool more = (kc + 1 < NC);
        float4 ra[4], rb[4];
        if (more) {
#pragma unroll
            for (int r = 0; r < 4; r++) {
                ra[r] = load_a<AMODE>(A, m0 + mrow + r * 32, kc + 1, kslot, lda);
                rb[r] = *(const float4*)(B + (long long)(n0 + mrow + r * 32) * ldb
                                           + (long long)(kc + 1) * 32 + kslot * 4);
            }
        }
        // ---- compute on buffer kc&1 ----
        const float* bufA = AsB[kc & 1];
        const float* bufB = BsB[kc & 1];
#pragma unroll
        for (int ks = 0; ks < 4; ks++) {
            const int k0 = ks * 8 + (lane & 3);
            uint32_t afr[2][4], bfr[8][2];
            const int ra0 = wm * 32 + (lane >> 2);
#pragma unroll
            for (int im = 0; im < 2; im++) {
                const int rr = ra0 + im * 16;
                afr[im][0] = __float_as_uint(bufA[ rr      * LDS_ROW + k0    ]);
                afr[im][1] = __float_as_uint(bufA[(rr + 8) * LDS_ROW + k0    ]);
                afr[im][2] = __float_as_uint(bufA[ rr      * LDS_ROW + k0 + 4]);
                afr[im][3] = __float_as_uint(bufA[(rr + 8) * LDS_ROW + k0 + 4]);
            }
#pragma unroll
            for (int in_ = 0; in_ < 8; in_++) {
                const int cb = wn * 64 + in_ * 8 + (lane >> 2);
                bfr[in_][0] = __float_as_uint(bufB[cb * LDS_ROW + k0    ]);
                bfr[in_][1] = __float_as_uint(bufB[cb * LDS_ROW + k0 + 4]);
            }
#pragma unroll
            for (int im = 0; im < 2; im++)
#pragma unroll
                for (int in_ = 0; in_ < 8; in_++)
                    mma_tf32(acc[im][in_], afr[im], bfr[in_]);
        }
        if (more) {
            float* dA = AsB[(kc + 1) & 1];
            float* dB = BsB[(kc + 1) & 1];
#pragma unroll
            for (int r = 0; r < 4; r++) {
                st_cvt(&dA[(mrow + r * 32) * LDS_ROW + kslot * 4], ra[r]);
                st_cvt(&dB[(mrow + r * 32) * LDS_ROW + kslot * 4], rb[r]);
            }
            __syncthreads();
        }
    }

    // ---- epilogue ----
#pragma unroll
    for (int im = 0; im < 2; im++) {
        const long long rbase = m0 + wm * 32 + im * 16 + (lane >> 2);
#pragma unroll
        for (int half = 0; half < 2; half++) {
            const long long r = rbase + half * 8;
#pragma unroll
            for (int in_ = 0; in_ < 8; in_++) {
                const int col = n0 + wn * 64 + in_ * 8 + (lane & 3) * 2;
                float2 o;
                o.x = acc[im][in_][half * 2 + 0] + bias[col];
                o.y = acc[im][in_][half * 2 + 1] + bias[col + 1];
                if (EPI >= 1) { o.x = fmaxf(o.x, 0.f); o.y = fmaxf(o.y, 0.f); }
                float2* cp = (float2*)(C + r * (long long)ldc + col);
                if (EPI == 2) {
                    float2 pv = *cp;
                    o.x += pv.x; o.y += pv.y;
                }
                *cp = o;
            }
        }
    }
}

// ---------------- token build ----------------
__global__ __launch_bounds__(256) void k_build(
    const float* __restrict__ s0, const float* __restrict__ s1, const float* __restrict__ s2,
    const float* __restrict__ p0, const float* __restrict__ p1, const float* __restrict__ p2,
    const float* __restrict__ lev, float* __restrict__ out, float* __restrict__ posf)
{
    long long i = (long long)blockIdx.x * 256 + threadIdx.x;
    int c = (int)(i & 255);
    long long r = i >> 8;
    int q  = (int)(r % LQQ);
    int bt = (int)(r / LQQ);
    int l, H, qq;
    if (q < 256)       { l = 0; H = 16; qq = q; }
    else if (q < 1280) { l = 1; H = 32; qq = q - 256; }
    else               { l = 2; H = 64; qq = q - 1280; }
    const float* s = (l == 0) ? s0 : (l == 1 ? s1 : s2);
    const float* p = (l == 0) ? p0 : (l == 1 ? p1 : p2);
    long long src = ((long long)(bt * CC + c)) * H * H + qq;
    out[i]  = s[src];
    posf[i] = p[src] + lev[l * CC + c];
}

__global__ __launch_bounds__(256) void k_addq(const float* __restrict__ a, const float* __restrict__ b,
                                              float* __restrict__ c)
{
    long long i = (long long)blockIdx.x * 256 + threadIdx.x;
    c[i] = a[i] + b[i];
}

// ---------------- deformable sampling (padded strides: off 256/row, aw 128/row) ----------------
__global__ __launch_bounds__(256) void k_sample(
    const float* __restrict__ v, const float* __restrict__ off,
    const float* __restrict__ aw, float* __restrict__ acc)
{
    int bq   = blockIdx.x;
    int h    = threadIdx.x >> 5;
    int lane = threadIdx.x & 31;
    int bt = bq / LQQ, q = bq % LQQ;

    int Hq, qq;
    if (q < 256)       { Hq = 16; qq = q; }
    else if (q < 1280) { Hq = 32; qq = q - 256; }
    else               { Hq = 64; qq = q - 1280; }
    float rx = ((qq % Hq) + 0.5f) / (float)Hq;
    float ry = ((qq / Hq) + 0.5f) / (float)Hq;

    const float* awp = aw + (long long)bq * 128 + h * 12;
    float a[12];
    float m = -1e30f;
#pragma unroll
    for (int j = 0; j < 12; j++) { a[j] = awp[j]; m = fmaxf(m, a[j]); }
    float s = 0.f;
#pragma unroll
    for (int j = 0; j < 12; j++) { a[j] = __expf(a[j] - m); s += a[j]; }
    float inv = 1.f / s;

    const float* offp = off + (long long)bq * 256 + h * 24;
    float sum = 0.f;
    const int starts[3] = {0, 256, 1280};
    const int hs[3]     = {16, 32, 64};

#pragma unroll
    for (int l = 0; l < 3; l++) {
        int H = hs[l], W = hs[l];
        const float* vl = v + ((long long)bt * LQQ + starts[l]) * CC + h * 32 + lane;
#pragma unroll
        for (int p = 0; p < 4; p++) {
            float ox = offp[(l * 4 + p) * 2 + 0];
            float oy = offp[(l * 4 + p) * 2 + 1];
            float x = rx * W + ox - 0.5f;
            float y = ry * H + oy - 0.5f;
            float x0f = floorf(x), y0f = floorf(y);
            int x0 = (int)x0f, y0 = (int)y0f;
            float fx = x - x0f, fy = y - y0f;
            float w00 = (1.f - fx) * (1.f - fy);
            float w01 = fx * (1.f - fy);
            float w10 = (1.f - fx) * fy;
            float w11 = fx * fy;
            float g = 0.f;
            if (y0 >= 0 && y0 < H) {
                if (x0 >= 0 && x0 < W)         g += w00 * vl[(long long)(y0 * W + x0) * CC];
                if (x0 + 1 >= 0 && x0 + 1 < W) g += w01 * vl[(long long)(y0 * W + x0 + 1) * CC];
            }
            if (y0 + 1 >= 0 && y0 + 1 < H) {
                if (x0 >= 0 && x0 < W)         g += w10 * vl[(long long)((y0 + 1) * W + x0) * CC];
                if (x0 + 1 >= 0 && x0 + 1 < W) g += w11 * vl[(long long)((y0 + 1) * W + x0 + 1) * CC];
            }
            sum += (a[l * 4 + p] * inv) * g;
        }
    }
    acc[(long long)bq * CC + h * 32 + lane] = sum;
}

// ---------------- layernorm ----------------
__global__ __launch_bounds__(256) void k_ln(
    const float* __restrict__ res, const float* __restrict__ delta,
    const float* __restrict__ g, const float* __restrict__ b,
    float* __restrict__ out)
{
    int row = blockIdx.x, c = threadIdx.x;
    long long idx = (long long)row * CC + c;
    float x = res[idx] + delta[idx];
    float s1 = x, s2 = x * x;
#pragma unroll
    for (int o = 16; o; o >>= 1) {
        s1 += __shfl_xor_sync(0xffffffffu, s1, o);
        s2 += __shfl_xor_sync(0xffffffffu, s2, o);
    }
    __shared__ float a1[8], a2[8];
    int wid = c >> 5, ln = c & 31;
    if (ln == 0) { a1[wid] = s1; a2[wid] = s2; }
    __syncthreads();
    float S1 = 0.f, S2 = 0.f;
#pragma unroll
    for (int k = 0; k < 8; k++) { S1 += a1[k]; S2 += a2[k]; }
    float mean = S1 * (1.f / 256.f);
    float var  = S2 * (1.f / 256.f) - mean * mean;
    float r = rsqrtf(var + 1e-5f);
    out[idx] = (x - mean) * r * g[c] + b[c];
}

// ---------------- bilinear upsample(64->128) add into x_tok (bt,p,c) ----------------
__global__ __launch_bounds__(256) void k_upadd(const float* __restrict__ outp, float* __restrict__ x)
{
    long long i = (long long)blockIdx.x * 256 + threadIdx.x;
    int c  = (int)(i & 255);
    int p  = (int)((i >> 8) & 16383);
    int bt = (int)(i >> 22);
    int w = p & 127, h = p >> 7;
    float sx = fminf(fmaxf(w * 0.5f - 0.25f, 0.f), 63.f);
    float sy = fminf(fmaxf(h * 0.5f - 0.25f, 0.f), 63.f);
    int x0 = (int)sx, y0 = (int)sy;
    int x1 = min(x0 + 1, 63), y1 = min(y0 + 1, 63);
    float fx = sx - x0, fy = sy - y0;
    const float* base = outp + ((long long)bt * LQQ + 1280) * CC + c;
    float v00 = base[(long long)(y0 * 64 + x0) * CC];
    float v01 = base[(long long)(y0 * 64 + x1) * CC];
    float v10 = base[(long long)(y1 * 64 + x0) * CC];
    float v11 = base[(long long)(y1 * 64 + x1) * CC];
    x[i] += v00 * (1.f - fx) * (1.f - fy) + v01 * fx * (1.f - fy)
          + v10 * (1.f - fx) * fy + v11 * fx * fy;
}

// ---------------- mask (B,C,T,H,W) <-> token (bt,p,c) transposes ----------------
__global__ __launch_bounds__(256) void k_trpix(const float* __restrict__ src, float* __restrict__ dst, int dir)
{
    __shared__ float t[32][33];
    int tx = threadIdx.x & 31, ty = threadIdx.x >> 5;
    int p0 = blockIdx.x << 5;
    int c0 = blockIdx.y << 5;
    int bt = blockIdx.z;
    int b = bt >> 1, tt = bt & 1;
    if (dir == 0) {
#pragma unroll
        for (int r = 0; r < 4; r++) {
            int c = c0 + ty + r * 8;
            t[ty + r * 8][tx] = src[(((long long)(b * CC + c)) * 2 + tt) * NPIX + p0 + tx];
        }
        __syncthreads();
#pragma unroll
        for (int r = 0; r < 4; r++) {
            int p = p0 + ty + r * 8;
            dst[((long long)bt * NPIX + p) * CC + c0 + tx] = t[tx][ty + r * 8];
        }
    } else {
#pragma unroll
        for (int r = 0; r < 4; r++) {
            int p = p0 + ty + r * 8;
            t[ty + r * 8][tx] = src[((long long)bt * NPIX + p) * CC + c0 + tx];
        }
        __syncthreads();
#pragma unroll
        for (int r = 0; r < 4; r++) {
            int c = c0 + ty + r * 8;
            dst[(((long long)(b * CC + c)) * 2 + tt) * NPIX + p0 + tx] = t[tx][ty + r * 8];
        }
    }
}

// ---------------- weight transposes: dst[l][n][k] = (n<Nsrc)? src[l][k][n] : 0 ----------------
__global__ __launch_bounds__(256) void k_trw(const float* __restrict__ src, float* __restrict__ dst,
                                             int K, int Nsrc, int Npad)
{
    int l = blockIdx.y;
    long long i = (long long)blockIdx.x * 256 + threadIdx.x;
    int k = (int)(i % K);
    int n = (int)(i / K);
    dst[(long long)l * Npad * K + i] = (n < Nsrc) ? src[(long long)l * K * Nsrc + (long long)k * Nsrc + n] : 0.f;
}

// conv weights: dst[l][o][r*256+ci] = w[l][o][ci][3x3 r]
__global__ __launch_bounds__(256) void k_trcv(const float* __restrict__ w, float* __restrict__ dst)
{
    int l = blockIdx.y;
    long long i = (long long)blockIdx.x * 256 + threadIdx.x;   // 256*2304 per layer
    int kk = (int)(i % KCONV);
    int o  = (int)(i / KCONV);
    int r  = kk >> 8, ci = kk & 255;
    dst[(long long)l * CC * KCONV + i] = w[(((long long)l * CC + o) * CC + ci) * 9 + r];
}

__global__ __launch_bounds__(256) void k_padb(const float* __restrict__ src, float* __restrict__ dst,
                                              int Nsrc, int Npad)
{
    int l = blockIdx.y;
    int i = blockIdx.x * 256 + threadIdx.x;
    if (i < Npad) dst[l * Npad + i] = (i < Nsrc) ? src[l * Nsrc + i] : 0.f;
}

// ---------------- host launcher ----------------
extern "C" void kernel_launch(void* const* d_in, const int* in_sizes, int n_in,
                              void* d_out, int out_size)
{
    const float *src0, *src1, *src2, *pos0, *pos1, *pos2;
    if (in_sizes[1] == in_sizes[0]) {
        src0 = (const float*)d_in[0]; pos0 = (const float*)d_in[1];
        src1 = (const float*)d_in[2]; pos1 = (const float*)d_in[3];
        src2 = (const float*)d_in[4]; pos2 = (const float*)d_in[5];
    } else {
        src0 = (const float*)d_in[0]; src1 = (const float*)d_in[1]; src2 = (const float*)d_in[2];
        pos0 = (const float*)d_in[3]; pos1 = (const float*)d_in[4]; pos2 = (const float*)d_in[5];
    }
    const float* mf     = (const float*)d_in[6];
    const float* lev    = (const float*)d_in[7];
    const float* off_w  = (const float*)d_in[8];
    const float* off_b  = (const float*)d_in[9];
    const float* aw_w   = (const float*)d_in[10];
    const float* aw_b   = (const float*)d_in[11];
    const float* val_w  = (const float*)d_in[12];
    const float* val_b  = (const float*)d_in[13];
    const float* out_w  = (const float*)d_in[14];
    const float* out_b  = (const float*)d_in[15];
    const float* ln1_g  = (const float*)d_in[16];
    const float* ln1_b  = (const float*)d_in[17];
    const float* ff1_w  = (const float*)d_in[18];
    const float* ff1_b  = (const float*)d_in[19];
    const float* ff2_w  = (const float*)d_in[20];
    const float* ff2_b  = (const float*)d_in[21];
    const float* ln2_g  = (const float*)d_in[22];
    const float* ln2_b  = (const float*)d_in[23];
    const float* lat_w  = (const float*)d_in[24];
    const float* lat_b  = (const float*)d_in[25];
    const float* outc_w = (const float*)d_in[26];
    const float* outc_b = (const float*)d_in[27];

    float* outp = (float*)d_out;
    float* mask = outp + (size_t)ROWS_TOK * CC;

    cudaFuncSetAttribute(k_mma<0,0>, cudaFuncAttributeMaxDynamicSharedMemorySize, SMEM_MMA);
    cudaFuncSetAttribute(k_mma<0,1>, cudaFuncAttributeMaxDynamicSharedMemorySize, SMEM_MMA);
    cudaFuncSetAttribute(k_mma<1,2>, cudaFuncAttributeMaxDynamicSharedMemorySize, SMEM_MMA);

    float *posf, *qb, *vb, *offb, *awb, *accb, *tmpb, *ffb, *xtok, *mtok;
    float *valT, *offT, *awT, *outT, *ff1T, *ff2T, *cvT, *offbp, *awbp;
    cudaGetSymbolAddress((void**)&posf, g_posf);
    cudaGetSymbolAddress((void**)&qb,   g_q);
    cudaGetSymbolAddress((void**)&vb,   g_v);
    cudaGetSymbolAddress((void**)&offb, g_off);
    cudaGetSymbolAddress((void**)&awb,  g_aw);
    cudaGetSymbolAddress((void**)&accb, g_acc);
    cudaGetSymbolAddress((void**)&tmpb, g_tmp);
    cudaGetSymbolAddress((void**)&ffb,  g_ff);
    cudaGetSymbolAddress((void**)&xtok, g_xtok);
    cudaGetSymbolAddress((void**)&mtok, g_mtok);
    cudaGetSymbolAddress((void**)&valT, g_valT);
    cudaGetSymbolAddress((void**)&offT, g_offT);
    cudaGetSymbolAddress((void**)&awT,  g_awT);
    cudaGetSymbolAddress((void**)&outT, g_outT);
    cudaGetSymbolAddress((void**)&ff1T, g_ff1T);
    cudaGetSymbolAddress((void**)&ff2T, g_ff2T);
    cudaGetSymbolAddress((void**)&cvT,  g_cvT);
    cudaGetSymbolAddress((void**)&offbp,g_offb);
    cudaGetSymbolAddress((void**)&awbp, g_awb);

    // ---- prologue: tokens, mask transpose, weight transposes ----
    k_build<<<ROWS_TOK, 256>>>(src0, src1, src2, pos0, pos1, pos2, lev, outp, posf);
    k_trpix<<<dim3(512, 8, 4), 256>>>(mf, mtok, 0);
    k_trw<<<dim3(65536/256,  NLAYERS), 256>>>(val_w, valT, 256, 256, 256);
    k_trw<<<dim3(65536/256,  NLAYERS), 256>>>(off_w, offT, 256, 192, 256);
    k_trw<<<dim3(32768/256,  NLAYERS), 256>>>(aw_w,  awT,  256,  96, 128);
    k_trw<<<dim3(65536/256,  NLAYERS), 256>>>(out_w, outT, 256, 256, 256);
    k_trw<<<dim3(262144/256, NLAYERS), 256>>>(ff1_w, ff1T, 256, 1024, 1024);
    k_trw<<<dim3(262144/256, NLAYERS), 256>>>(ff2_w, ff2T, 1024, 256, 256);
    k_trcv<<<dim3(589824/256, NLAYERS), 256>>>(outc_w, cvT);
    k_padb<<<dim3(1, NLAYERS), 256>>>(off_b, offbp, 192, 256);
    k_padb<<<dim3(1, NLAYERS), 256>>>(aw_b,  awbp,   96, 128);

    const int MT = ROWS_TOK / 128;   // 168
    const int MP = ROWS_PIX / 128;   // 512

    for (int i = 0; i < NLAYERS; i++) {
        k_addq<<<ROWS_TOK, 256>>>(outp, posf, qb);

        k_mma<0,0><<<dim3(2, MT), 256, SMEM_MMA>>>(outp, valT + (long long)i*65536,  val_b + i*256, vb,   256, 256, 256, 256);
        k_mma<0,0><<<dim3(2, MT), 256, SMEM_MMA>>>(qb,   offT + (long long)i*65536,  offbp + i*256, offb, 256, 256, 256, 256);
        k_mma<0,0><<<dim3(1, MT), 256, SMEM_MMA>>>(qb,   awT  + (long long)i*32768,  awbp  + i*128, awb,  256, 256, 256, 128);

        k_sample<<<ROWS_TOK, 256>>>(vb, offb, awb, accb);

        k_mma<0,0><<<dim3(2, MT), 256, SMEM_MMA>>>(accb, outT + (long long)i*65536,  out_b + i*256, tmpb, 256, 256, 256, 256);
        k_ln<<<ROWS_TOK, 256>>>(outp, tmpb, ln1_g + i*256, ln1_b + i*256, outp);

        k_mma<0,1><<<dim3(8, MT), 256, SMEM_MMA>>>(outp, ff1T + (long long)i*262144, ff1_b + i*1024, ffb, 256, 256, 256, 1024);
        k_mma<0,0><<<dim3(2, MT), 256, SMEM_MMA>>>(ffb,  ff2T + (long long)i*262144, ff2_b + i*256, tmpb, 1024, 1024, 1024, 256);
        k_ln<<<ROWS_TOK, 256>>>(outp, tmpb, ln2_g + i*256, ln2_b + i*256, outp);

        // FPN: x_tok = lateral(mask_tok) + bias ; += upsample ; mask_tok += relu(conv3x3(x_tok)+b)
        k_mma<0,0><<<dim3(2, MP), 256, SMEM_MMA>>>(mtok, lat_w + (long long)i*65536, lat_b + i*256, xtok, 256, 256, 256, 256);
        k_upadd<<<ROWS_PIX, 256>>>(outp, xtok);
        k_mma<1,2><<<dim3(2, MP), 256, SMEM_MMA>>>(xtok, cvT + (long long)i*589824, outc_b + i*256, mtok, KCONV, 0, KCONV, 256);
    }

    // ---- epilogue: mask tokens back to (B,C,T,H,W) ----
    k_trpix<<<dim3(512, 8, 4), 256>>>(mtok, mask, 1);
}

// round 4
// speedup vs baseline: 2.5885x; 1.1942x over previous
#include <cuda_runtime.h>
#include <cstdint>
#include <math.h>

// ---------------- problem constants ----------------
#define CC        256
#define LQQ       5376
#define BTT       4
#define NLAYERS   6
#define NPIX      16384
#define ROWS_TOK  (BTT*LQQ)     // 21504 = 168*128
#define ROWS_PIX  (BTT*NPIX)    // 65536 = 512*128
#define KCONV     2304

// ---------------- scratch (device globals) ----------------
__device__ float g_posf[ROWS_TOK*CC];
__device__ float g_q   [ROWS_TOK*CC];
__device__ float g_v   [ROWS_TOK*CC];
__device__ float g_off [ROWS_TOK*256];
__device__ float g_aw  [ROWS_TOK*128];
__device__ float g_acc [ROWS_TOK*CC];
__device__ float g_tmp [ROWS_TOK*CC];
__device__ float g_ff  [ROWS_TOK*1024];
__device__ float g_xtok[ (long long)ROWS_PIX*CC ];
__device__ float g_mtok[ (long long)ROWS_PIX*CC ];
__device__ float g_valT[NLAYERS*65536];
__device__ float g_offT[NLAYERS*65536];
__device__ float g_awT [NLAYERS*32768];
__device__ float g_outT[NLAYERS*65536];
__device__ float g_ff1T[NLAYERS*262144];
__device__ float g_ff2T[NLAYERS*262144];
__device__ float g_cvT [NLAYERS*589824];
__device__ float g_offb[NLAYERS*256];
__device__ float g_awb [NLAYERS*128];

// ---------------- helpers ----------------
__device__ __forceinline__ float tf32f(float x){
    uint32_t u; asm("cvt.rna.tf32.f32 %0, %1;" : "=r"(u) : "f"(x)); return __uint_as_float(u);
}
__device__ __forceinline__ void mma_tf32(float* d, const uint32_t* a, const uint32_t* b){
    asm volatile("mma.sync.aligned.m16n8k8.row.col.f32.tf32.tf32.f32 "
        "{%0,%1,%2,%3}, {%4,%5,%6,%7}, {%8,%9}, {%0,%1,%2,%3};"
        : "+f"(d[0]), "+f"(d[1]), "+f"(d[2]), "+f"(d[3])
        : "r"(a[0]), "r"(a[1]), "r"(a[2]), "r"(a[3]), "r"(b[0]), "r"(b[1]));
}
__device__ __forceinline__ uint32_t smem_u32(const void* p){
    uint32_t a; asm("{ .reg .u64 t; cvta.to.shared.u64 t, %1; cvt.u32.u64 %0, t; }" : "=r"(a) : "l"(p)); return a;
}
__device__ __forceinline__ void cpa16(uint32_t dst, const void* src, bool ok){
    int sz = ok ? 16 : 0;
    asm volatile("cp.async.cg.shared.global [%0], [%1], 16, %2;\n"
                 :: "r"(dst), "l"(src), "r"(sz) : "memory");
}
#define CPA_COMMIT() asm volatile("cp.async.commit_group;" ::: "memory")
#define CPA_WAIT(n)  asm volatile("cp.async.wait_group %0;" :: "n"(n) : "memory")

// ---------------- GEMM: C[M,N] = A[M,K] * B^T (B NxK K-major, stride K) + bias --------
// Inputs MUST be pre-rounded to tf32. BM=BN=128, BK=32, 256 thr, 8 warps (4x2), warp 32x64.
// 3-stage cp.async pipeline. AMODE 0: A row-major (lda). AMODE 1: conv3x3 gather from
// x_tok (bt,128,128,256), K=2304.
// EPI 0: C=acc+bias; 1: C=round(relu(acc+bias)); 2: C=round(C+relu(acc+bias));
// EPI 3: C=round(acc+bias+bilinear_up(up)).
#define LDSR 36
#define STF  (128*LDSR)                // 4608 floats per tile-stage
#define SMEM_MMA (3*2*STF*4)           // 110592 bytes

template<int AMODE>
__device__ __forceinline__ void issue_tile(
    const float* __restrict__ A, const float* __restrict__ B,
    uint32_t smA, uint32_t smB, int kc, long long m0, int n0, int lda, int ldbK, int tid)
{
    const int row = tid >> 1;
    const int sl0 = (tid & 1) * 4;
#pragma unroll
    for (int j = 0; j < 4; j++) {
        const int slot = sl0 + j;
        const uint32_t da = smA + (uint32_t)(row * LDSR + slot * 4) * 4u;
        if (AMODE == 0) {
            cpa16(da, A + (m0 + row) * (long long)lda + kc * 32 + slot * 4, true);
        } else {
            const long long grow = m0 + row;
            const int bt = (int)(grow >> 14);
            const int p  = (int)(grow & 16383);
            const int hh = p >> 7, ww = p & 127;
            const int k  = kc * 32 + slot * 4;
            const int r3 = k >> 8, ci = k & 255;
            const int q3 = r3 / 3;
            const int h2 = hh + q3 - 1, w2 = ww + (r3 - q3 * 3) - 1;
            const bool ok = ((unsigned)h2 < 128u) && ((unsigned)w2 < 128u);
            cpa16(da, A + ((((long long)bt << 7) + h2) * 128 + w2) * 256 + ci, ok);
        }
        const uint32_t db = smB + (uint32_t)(row * LDSR + slot * 4) * 4u;
        cpa16(db, B + (long long)(n0 + row) * ldbK + kc * 32 + slot * 4, true);
    }
}

template<int AMODE, int EPI>
__global__ void __launch_bounds__(256, 2) k_mma(
    const float* __restrict__ A, const float* __restrict__ B,
    const float* __restrict__ bias, float* __restrict__ C,
    const float* __restrict__ up, int K, int lda, int ldc)
{
    extern __shared__ float sm[];
    const uint32_t smbase = smem_u32(sm);

    const int tid  = threadIdx.x;
    const int lane = tid & 31;
    const int wid  = tid >> 5;
    const int wm   = wid >> 1;          // 0..3
    const int wn   = wid & 1;           // 0..1
    const long long m0 = (long long)blockIdx.y * 128;
    const int n0 = blockIdx.x * 128;
    const int NC = K >> 5;

    // prologue: fill up to 3 stages
#pragma unroll
    for (int s = 0; s < 3; s++) {
        if (s < NC) {
            issue_tile<AMODE>(A, B, smbase + (uint32_t)(s*2*STF)*4u,
                              smbase + (uint32_t)((s*2+1)*STF)*4u, s, m0, n0, lda, K, tid);
            CPA_COMMIT();
        }
    }

    float acc[2][8][4];
#pragma unroll
    for (int i = 0; i < 2; i++)
#pragma unroll
        for (int j = 0; j < 8; j++)
#pragma unroll
            for (int t = 0; t < 4; t++) acc[i][j][t] = 0.f;

    for (int kc = 0; kc < NC; kc++) {
        const int st = kc % 3;
        const int rem = NC - kc;
        if (rem >= 3)      CPA_WAIT(2);
        else if (rem == 2) CPA_WAIT(1);
        else               CPA_WAIT(0);
        __syncthreads();

        const float* bufA = sm + st * 2 * STF;
        const float* bufB = bufA + STF;
#pragma unroll
        for (int ks = 0; ks < 4; ks++) {
            const int k0 = ks * 8 + (lane & 3);
            uint32_t afr[2][4], bfr[8][2];
            const int ra0 = wm * 32 + (lane >> 2);
#pragma unroll
            for (int im = 0; im < 2; im++) {
                const int rr = ra0 + im * 16;
                afr[im][0] = __float_as_uint(bufA[ rr      * LDSR + k0    ]);
                afr[im][1] = __float_as_uint(bufA[(rr + 8) * LDSR + k0    ]);
                afr[im][2] = __float_as_uint(bufA[ rr      * LDSR + k0 + 4]);
                afr[im][3] = __float_as_uint(bufA[(rr + 8) * LDSR + k0 + 4]);
            }
#pragma unroll
            for (int in_ = 0; in_ < 8; in_++) {
                const int cb = wn * 64 + in_ * 8 + (lane >> 2);
                bfr[in_][0] = __float_as_uint(bufB[cb * LDSR + k0    ]);
                bfr[in_][1] = __float_as_uint(bufB[cb * LDSR + k0 + 4]);
            }
#pragma unroll
            for (int im = 0; im < 2; im++)
#pragma unroll
                for (int in_ = 0; in_ < 8; in_++)
                    mma_tf32(acc[im][in_], afr[im], bfr[in_]);
        }
        __syncthreads();
        if (kc + 3 < NC) {
            issue_tile<AMODE>(A, B, smbase + (uint32_t)(st*2*STF)*4u,
                              smbase + (uint32_t)((st*2+1)*STF)*4u, kc + 3, m0, n0, lda, K, tid);
            CPA_COMMIT();
        }
    }

    // ---- epilogue ----
#pragma unroll
    for (int im = 0; im < 2; im++) {
        const long long rbase = m0 + wm * 32 + im * 16 + (lane >> 2);
#pragma unroll
        for (int half = 0; half < 2; half++) {
            const long long r = rbase + half * 8;
            // bilinear setup for EPI 3
            float fx = 0.f, fy = 0.f;
            const float* ub = nullptr;
            int x0 = 0, x1 = 0, y0 = 0, y1 = 0;
            if (EPI == 3) {
                const int bt = (int)(r >> 14);
                const int p  = (int)(r & 16383);
                const int w = p & 127, h = p >> 7;
                float sx = fminf(fmaxf(w * 0.5f - 0.25f, 0.f), 63.f);
                float sy = fminf(fmaxf(h * 0.5f - 0.25f, 0.f), 63.f);
                x0 = (int)sx; y0 = (int)sy;
                x1 = min(x0 + 1, 63); y1 = min(y0 + 1, 63);
                fx = sx - x0; fy = sy - y0;
                ub = up + ((long long)bt * LQQ + 1280) * 256;
            }
#pragma unroll
            for (int in_ = 0; in_ < 8; in_++) {
                const int col = n0 + wn * 64 + in_ * 8 + (lane & 3) * 2;
                float2 o;
                o.x = acc[im][in_][half * 2 + 0] + bias[col];
                o.y = acc[im][in_][half * 2 + 1] + bias[col + 1];
                if (EPI == 1 || EPI == 2) { o.x = fmaxf(o.x, 0.f); o.y = fmaxf(o.y, 0.f); }
                float2* cp = (float2*)(C + r * (long long)ldc + col);
                if (EPI == 2) {
                    float2 pv = *cp;
                    o.x += pv.x; o.y += pv.y;
                }
                if (EPI == 3) {
                    const float w00 = (1.f - fx) * (1.f - fy), w01 = fx * (1.f - fy);
                    const float w10 = (1.f - fx) * fy,         w11 = fx * fy;
                    const float* p00 = ub + (y0 * 64 + x0) * 256 + col;
                    const float* p01 = ub + (y0 * 64 + x1) * 256 + col;
                    const float* p10 = ub + (y1 * 64 + x0) * 256 + col;
                    const float* p11 = ub + (y1 * 64 + x1) * 256 + col;
                    o.x += w00 * p00[0] + w01 * p01[0] + w10 * p10[0] + w11 * p11[0];
                    o.y += w00 * p00[1] + w01 * p01[1] + w10 * p10[1] + w11 * p11[1];
                }
                if (EPI >= 1) { o.x = tf32f(o.x); o.y = tf32f(o.y); }
                *cp = o;
            }
        }
    }
}

// ---------------- token build: out (rounded), posf, q0 = round(out+posf) --------------
__global__ __launch_bounds__(256) void k_build(
    const float* __restrict__ s0, const float* __restrict__ s1, const float* __restrict__ s2,
    const float* __restrict__ p0, const float* __restrict__ p1, const float* __restrict__ p2,
    const float* __restrict__ lev, float* __restrict__ out, float* __restrict__ posf,
    float* __restrict__ q0)
{
    long long i = (long long)blockIdx.x * 256 + threadIdx.x;
    int c = (int)(i & 255);
    long long r = i >> 8;
    int q  = (int)(r % LQQ);
    int bt = (int)(r / LQQ);
    int l, H, qq;
    if (q < 256)       { l = 0; H = 16; qq = q; }
    else if (q < 1280) { l = 1; H = 32; qq = q - 256; }
    else               { l = 2; H = 64; qq = q - 1280; }
    const float* s = (l == 0) ? s0 : (l == 1 ? s1 : s2);
    const float* p = (l == 0) ? p0 : (l == 1 ? p1 : p2);
    long long src = ((long long)(bt * CC + c)) * H * H + qq;
    float sv = s[src];
    float pv = p[src] + lev[l * CC + c];
    out[i]  = tf32f(sv);
    posf[i] = pv;
    q0[i]   = tf32f(sv + pv);
}

// ---------------- deformable sampling ----------------
__global__ __launch_bounds__(256) void k_sample(
    const float* __restrict__ v, const float* __restrict__ off,
    const float* __restrict__ aw, float* __restrict__ acc)
{
    int bq   = blockIdx.x;
    int h    = threadIdx.x >> 5;
    int lane = threadIdx.x & 31;
    int bt = bq / LQQ, q = bq % LQQ;

    int Hq, qq;
    if (q < 256)       { Hq = 16; qq = q; }
    else if (q < 1280) { Hq = 32; qq = q - 256; }
    else               { Hq = 64; qq = q - 1280; }
    float rx = ((qq % Hq) + 0.5f) / (float)Hq;
    float ry = ((qq / Hq) + 0.5f) / (float)Hq;

    const float* awp = aw + (long long)bq * 128 + h * 12;
    float a[12];
    float m = -1e30f;
#pragma unroll
    for (int j = 0; j < 12; j++) { a[j] = awp[j]; m = fmaxf(m, a[j]); }
    float s = 0.f;
#pragma unroll
    for (int j = 0; j < 12; j++) { a[j] = __expf(a[j] - m); s += a[j]; }
    float inv = 1.f / s;

    const float* offp = off + (long long)bq * 256 + h * 24;
    float sum = 0.f;
    const int starts[3] = {0, 256, 1280};
    const int hs[3]     = {16, 32, 64};

#pragma unroll
    for (int l = 0; l < 3; l++) {
        int H = hs[l], W = hs[l];
        const float* vl = v + ((long long)bt * LQQ + starts[l]) * CC + h * 32 + lane;
#pragma unroll
        for (int p = 0; p < 4; p++) {
            float ox = offp[(l * 4 + p) * 2 + 0];
            float oy = offp[(l * 4 + p) * 2 + 1];
            float x = rx * W + ox - 0.5f;
            float y = ry * H + oy - 0.5f;
            float x0f = floorf(x), y0f = floorf(y);
            int x0 = (int)x0f, y0 = (int)y0f;
            float fx = x - x0f, fy = y - y0f;
            float w00 = (1.f - fx) * (1.f - fy);
            float w01 = fx * (1.f - fy);
            float w10 = (1.f - fx) * fy;
            float w11 = fx * fy;
            float g = 0.f;
            if (y0 >= 0 && y0 < H) {
                if (x0 >= 0 && x0 < W)         g += w00 * vl[(long long)(y0 * W + x0) * CC];
                if (x0 + 1 >= 0 && x0 + 1 < W) g += w01 * vl[(long long)(y0 * W + x0 + 1) * CC];
            }
            if (y0 + 1 >= 0 && y0 + 1 < H) {
                if (x0 >= 0 && x0 < W)         g += w10 * vl[(long long)((y0 + 1) * W + x0) * CC];
                if (x0 + 1 >= 0 && x0 + 1 < W) g += w11 * vl[(long long)((y0 + 1) * W + x0 + 1) * CC];
            }
            sum += (a[l * 4 + p] * inv) * g;
        }
    }
    acc[(long long)bq * CC + h * 32 + lane] = tf32f(sum);
}

// ---------------- layernorm (rounded out; optional q = round(out+posf)) --------------
template<int QOUT>
__global__ __launch_bounds__(256) void k_ln(
    const float* __restrict__ res, const float* __restrict__ delta,
    const float* __restrict__ g, const float* __restrict__ b,
    float* __restrict__ out, const float* __restrict__ posf, float* __restrict__ qout)
{
    int row = blockIdx.x, c = threadIdx.x;
    long long idx = (long long)row * CC + c;
    float x = res[idx] + delta[idx];
    float s1 = x, s2 = x * x;
#pragma unroll
    for (int o = 16; o; o >>= 1) {
        s1 += __shfl_xor_sync(0xffffffffu, s1, o);
        s2 += __shfl_xor_sync(0xffffffffu, s2, o);
    }
    __shared__ float a1[8], a2[8];
    int wid = c >> 5, ln = c & 31;
    if (ln == 0) { a1[wid] = s1; a2[wid] = s2; }
    __syncthreads();
    float S1 = 0.f, S2 = 0.f;
#pragma unroll
    for (int k = 0; k < 8; k++) { S1 += a1[k]; S2 += a2[k]; }
    float mean = S1 * (1.f / 256.f);
    float var  = S2 * (1.f / 256.f) - mean * mean;
    float r = rsqrtf(var + 1e-5f);
    float y = (x - mean) * r * g[c] + b[c];
    out[idx] = tf32f(y);
    if (QOUT) qout[idx] = tf32f(y + posf[idx]);
}

// ---------------- mask (B,C,T,H,W) <-> token (bt,p,c) transposes ----------------
__global__ __launch_bounds__(256) void k_trpix(const float* __restrict__ src, float* __restrict__ dst, int dir)
{
    __shared__ float t[32][33];
    int tx = threadIdx.x & 31, ty = threadIdx.x >> 5;
    int p0 = blockIdx.x << 5;
    int c0 = blockIdx.y << 5;
    int bt = blockIdx.z;
    int b = bt >> 1, tt = bt & 1;
    if (dir == 0) {
#pragma unroll
        for (int r = 0; r < 4; r++) {
            int c = c0 + ty + r * 8;
            t[ty + r * 8][tx] = src[(((long long)(b * CC + c)) * 2 + tt) * NPIX + p0 + tx];
        }
        __syncthreads();
#pragma unroll
        for (int r = 0; r < 4; r++) {
            int p = p0 + ty + r * 8;
            dst[((long long)bt * NPIX + p) * CC + c0 + tx] = tf32f(t[tx][ty + r * 8]);
        }
    } else {
#pragma unroll
        for (int r = 0; r < 4; r++) {
            int p = p0 + ty + r * 8;
            t[ty + r * 8][tx] = src[((long long)bt * NPIX + p) * CC + c0 + tx];
        }
        __syncthreads();
#pragma unroll
        for (int r = 0; r < 4; r++) {
            int c = c0 + ty + r * 8;
            dst[(((long long)(b * CC + c)) * 2 + tt) * NPIX + p0 + tx] = t[tx][ty + r * 8];
        }
    }
}

// ---------------- weight transposes (rounded): dst[l][n][k] = tf32(src[l][k][n]) -------
__global__ __launch_bounds__(256) void k_trw(const float* __restrict__ src, float* __restrict__ dst,
                                             int K, int Nsrc, int Npad)
{
    int l = blockIdx.y;
    long long i = (long long)blockIdx.x * 256 + threadIdx.x;
    int k = (int)(i % K);
    int n = (int)(i / K);
    dst[(long long)l * Npad * K + i] =
        (n < Nsrc) ? tf32f(src[(long long)l * K * Nsrc + (long long)k * Nsrc + n]) : 0.f;
}

// conv weights: dst[l][o][r*256+ci] = tf32(w[l][o][ci][3x3 r])
__global__ __launch_bounds__(256) void k_trcv(const float* __restrict__ w, float* __restrict__ dst)
{
    int l = blockIdx.y;
    long long i = (long long)blockIdx.x * 256 + threadIdx.x;   // 256*2304 per layer
    int kk = (int)(i % KCONV);
    int o  = (int)(i / KCONV);
    int r  = kk >> 8, ci = kk & 255;
    dst[(long long)l * CC * KCONV + i] = tf32f(w[(((long long)l * CC + o) * CC + ci) * 9 + r]);
}

__global__ __launch_bounds__(256) void k_padb(const float* __restrict__ src, float* __restrict__ dst,
                                              int Nsrc, int Npad)
{
    int l = blockIdx.y;
    int i = blockIdx.x * 256 + threadIdx.x;
    if (i < Npad) dst[l * Npad + i] = (i < Nsrc) ? src[l * Nsrc + i] : 0.f;
}

// ---------------- host launcher ----------------
extern "C" void kernel_launch(void* const* d_in, const int* in_sizes, int n_in,
                              void* d_out, int out_size)
{
    const float *src0, *src1, *src2, *pos0, *pos1, *pos2;
    if (in_sizes[1] == in_sizes[0]) {
        src0 = (const float*)d_in[0]; pos0 = (const float*)d_in[1];
        src1 = (const float*)d_in[2]; pos1 = (const float*)d_in[3];
        src2 = (const float*)d_in[4]; pos2 = (const float*)d_in[5];
    } else {
        src0 = (const float*)d_in[0]; src1 = (const float*)d_in[1]; src2 = (const float*)d_in[2];
        pos0 = (const float*)d_in[3]; pos1 = (const float*)d_in[4]; pos2 = (const float*)d_in[5];
    }
    const float* mf     = (const float*)d_in[6];
    const float* lev    = (const float*)d_in[7];
    const float* off_w  = (const float*)d_in[8];
    const float* off_b  = (const float*)d_in[9];
    const float* aw_w   = (const float*)d_in[10];
    const float* aw_b   = (const float*)d_in[11];
    const float* val_w  = (const float*)d_in[12];
    const float* val_b  = (const float*)d_in[13];
    const float* out_w  = (const float*)d_in[14];
    const float* out_b  = (const float*)d_in[15];
    const float* ln1_g  = (const float*)d_in[16];
    const float* ln1_b  = (const float*)d_in[17];
    const float* ff1_w  = (const float*)d_in[18];
    const float* ff1_b  = (const float*)d_in[19];
    const float* ff2_w  = (const float*)d_in[20];
    const float* ff2_b  = (const float*)d_in[21];
    const float* ln2_g  = (const float*)d_in[22];
    const float* ln2_b  = (const float*)d_in[23];
    const float* lat_w  = (const float*)d_in[24];
    const float* lat_b  = (const float*)d_in[25];
    const float* outc_w = (const float*)d_in[26];
    const float* outc_b = (const float*)d_in[27];

    float* outp = (float*)d_out;
    float* mask = outp + (size_t)ROWS_TOK * CC;

    cudaFuncSetAttribute(k_mma<0,0>, cudaFuncAttributeMaxDynamicSharedMemorySize, SMEM_MMA);
    cudaFuncSetAttribute(k_mma<0,1>, cudaFuncAttributeMaxDynamicSharedMemorySize, SMEM_MMA);
    cudaFuncSetAttribute(k_mma<0,3>, cudaFuncAttributeMaxDynamicSharedMemorySize, SMEM_MMA);
    cudaFuncSetAttribute(k_mma<1,2>, cudaFuncAttributeMaxDynamicSharedMemorySize, SMEM_MMA);

    float *posf, *qb, *vb, *offb, *awb, *accb, *tmpb, *ffb, *xtok, *mtok;
    float *valT, *offT, *awT, *outT, *ff1T, *ff2T, *cvT, *offbp, *awbp;
    cudaGetSymbolAddress((void**)&posf, g_posf);
    cudaGetSymbolAddress((void**)&qb,   g_q);
    cudaGetSymbolAddress((void**)&vb,   g_v);
    cudaGetSymbolAddress((void**)&offb, g_off);
    cudaGetSymbolAddress((void**)&awb,  g_aw);
    cudaGetSymbolAddress((void**)&accb, g_acc);
    cudaGetSymbolAddress((void**)&tmpb, g_tmp);
    cudaGetSymbolAddress((void**)&ffb,  g_ff);
    cudaGetSymbolAddress((void**)&xtok, g_xtok);
    cudaGetSymbolAddress((void**)&mtok, g_mtok);
    cudaGetSymbolAddress((void**)&valT, g_valT);
    cudaGetSymbolAddress((void**)&offT, g_offT);
    cudaGetSymbolAddress((void**)&awT,  g_awT);
    cudaGetSymbolAddress((void**)&outT, g_outT);
    cudaGetSymbolAddress((void**)&ff1T, g_ff1T);
    cudaGetSymbolAddress((void**)&ff2T, g_ff2T);
    cudaGetSymbolAddress((void**)&cvT,  g_cvT);
    cudaGetSymbolAddress((void**)&offbp,g_offb);
    cudaGetSymbolAddress((void**)&awbp, g_awb);

    // ---- prologue ----
    k_build<<<ROWS_TOK, 256>>>(src0, src1, src2, pos0, pos1, pos2, lev, outp, posf, qb);
    k_trpix<<<dim3(512, 8, 4), 256>>>(mf, mtok, 0);
    k_trw<<<dim3(65536/256,  NLAYERS), 256>>>(val_w, valT, 256, 256, 256);
    k_trw<<<dim3(65536/256,  NLAYERS), 256>>>(off_w, offT, 256, 192, 256);
    k_trw<<<dim3(32768/256,  NLAYERS), 256>>>(aw_w,  awT,  256,  96, 128);
    k_trw<<<dim3(65536/256,  NLAYERS), 256>>>(out_w, outT, 256, 256, 256);
    k_trw<<<dim3(262144/256, NLAYERS), 256>>>(ff1_w, ff1T, 256, 1024, 1024);
    k_trw<<<dim3(262144/256, NLAYERS), 256>>>(ff2_w, ff2T, 1024, 256, 256);
    k_trcv<<<dim3(589824/256, NLAYERS), 256>>>(outc_w, cvT);
    k_padb<<<dim3(1, NLAYERS), 256>>>(off_b, offbp, 192, 256);
    k_padb<<<dim3(1, NLAYERS), 256>>>(aw_b,  awbp,   96, 128);

    const int MT = ROWS_TOK / 128;   // 168
    const int MP = ROWS_PIX / 128;   // 512

    for (int i = 0; i < NLAYERS; i++) {
        // qb already holds round(outp + posf)
        k_mma<0,0><<<dim3(2, MT), 256, SMEM_MMA>>>(outp, valT + (long long)i*65536,  val_b + i*256, vb,   nullptr, 256, 256, 256);
        k_mma<0,0><<<dim3(2, MT), 256, SMEM_MMA>>>(qb,   offT + (long long)i*65536,  offbp + i*256, offb, nullptr, 256, 256, 256);
        k_mma<0,0><<<dim3(1, MT), 256, SMEM_MMA>>>(qb,   awT  + (long long)i*32768,  awbp  + i*128, awb,  nullptr, 256, 256, 128);

        k_sample<<<ROWS_TOK, 256>>>(vb, offb, awb, accb);

        k_mma<0,0><<<dim3(2, MT), 256, SMEM_MMA>>>(accb, outT + (long long)i*65536,  out_b + i*256, tmpb, nullptr, 256, 256, 256);
        k_ln<0><<<ROWS_TOK, 256>>>(outp, tmpb, ln1_g + i*256, ln1_b + i*256, outp, nullptr, nullptr);

        k_mma<0,1><<<dim3(8, MT), 256, SMEM_MMA>>>(outp, ff1T + (long long)i*262144, ff1_b + i*1024, ffb, nullptr, 256, 256, 1024);
        k_mma<0,0><<<dim3(2, MT), 256, SMEM_MMA>>>(ffb,  ff2T + (long long)i*262144, ff2_b + i*256, tmpb, nullptr, 1024, 1024, 256);
        k_ln<1><<<ROWS_TOK, 256>>>(outp, tmpb, ln2_g + i*256, ln2_b + i*256, outp, posf, qb);

        // FPN: x_tok = round(lat(mask_tok)+bias+upsample(outp)); mask_tok = round(mask_tok + relu(conv3x3(x_tok)+b))
        k_mma<0,3><<<dim3(2, MP), 256, SMEM_MMA>>>(mtok, lat_w + (long long)i*65536, lat_b + i*256, xtok, outp, 256, 256, 256);
        k_mma<1,2><<<dim3(2, MP), 256, SMEM_MMA>>>(xtok, cvT + (long long)i*589824, outc_b + i*256, mtok, nullptr, KCONV, 0, 256);
    }

    // ---- epilogue: mask tokens back to (B,C,T,H,W) ----
    k_trpix<<<dim3(512, 8, 4), 256>>>(mtok, mask, 1);
}

// round 5
// speedup vs baseline: 4.3134x; 1.6664x over previous
#include <cuda_runtime.h>
#include <cuda_fp16.h>
#include <cstdint>
#include <math.h>

// ---------------- problem constants ----------------
#define CC        256
#define LQQ       5376
#define BTT       4
#define NLAYERS   6
#define NPIX      16384
#define ROWS_TOK  (BTT*LQQ)     // 21504 = 168*128
#define ROWS_PIX  (BTT*NPIX)    // 65536 = 512*128
#define KCONV     2304

// ---------------- scratch (device globals) ----------------
__device__ float  g_posf[ROWS_TOK*CC];
__device__ float  g_off [ROWS_TOK*256];
__device__ float  g_aw  [ROWS_TOK*128];
__device__ float  g_tmp [ROWS_TOK*CC];
__device__ float  g_mtok[(long long)ROWS_PIX*CC];      // fp32 mask master (token layout)
__device__ __half g_outh[ROWS_TOK*CC];
__device__ __half g_qh  [ROWS_TOK*CC];
__device__ __half g_vh  [ROWS_TOK*CC];
__device__ __half g_acch[ROWS_TOK*CC];
__device__ __half g_ffh [ROWS_TOK*1024];
__device__ __half g_xh  [(long long)ROWS_PIX*CC];      // conv input (half)
__device__ __half g_mh  [(long long)ROWS_PIX*CC];      // mask half shadow (lat A input)
__device__ __half g_valT[NLAYERS*65536];
__device__ __half g_offT[NLAYERS*65536];
__device__ __half g_awT [NLAYERS*32768];
__device__ __half g_outT[NLAYERS*65536];
__device__ __half g_ff1T[NLAYERS*262144];
__device__ __half g_ff2T[NLAYERS*262144];
__device__ __half g_cvT [NLAYERS*589824];
__device__ __half g_latT[NLAYERS*65536];
__device__ float  g_offb[NLAYERS*256];
__device__ float  g_awb [NLAYERS*128];

// ---------------- helpers ----------------
__device__ __forceinline__ void mma_f16(float* d, const uint32_t* a, const uint32_t* b){
    asm volatile("mma.sync.aligned.m16n8k16.row.col.f32.f16.f16.f32 "
        "{%0,%1,%2,%3}, {%4,%5,%6,%7}, {%8,%9}, {%0,%1,%2,%3};"
        : "+f"(d[0]), "+f"(d[1]), "+f"(d[2]), "+f"(d[3])
        : "r"(a[0]), "r"(a[1]), "r"(a[2]), "r"(a[3]), "r"(b[0]), "r"(b[1]));
}
__device__ __forceinline__ uint32_t smem_u32(const void* p){
    uint32_t a; asm("{ .reg .u64 t; cvta.to.shared.u64 t, %1; cvt.u32.u64 %0, t; }" : "=r"(a) : "l"(p)); return a;
}
__device__ __forceinline__ void cpa16(uint32_t dst, const void* src, bool ok){
    int sz = ok ? 16 : 0;
    asm volatile("cp.async.cg.shared.global [%0], [%1], 16, %2;\n"
                 :: "r"(dst), "l"(src), "r"(sz) : "memory");
}
#define CPA_COMMIT() asm volatile("cp.async.commit_group;" ::: "memory")
#define CPA_WAIT(n)  asm volatile("cp.async.wait_group %0;" :: "n"(n) : "memory")

// ---------------- fp16 mma GEMM: C[M,N] = A[M,K] * B^T (B NxK K-major half) + bias ----
// BM=BN=128, BK=32, 256 thr, 8 warps (4x2), warp 32x64. 4-stage cp.async.
// AMODE 0: A row-major half (lda). AMODE 1: conv3x3 gather from xh (bt,128,128,256 half).
// EPI 0: float C = acc+bias
// EPI 1: half  C = relu(acc+bias)
// EPI 2: half  C = acc+bias
// EPI 3: half  C = acc+bias+bilinear_up(up fp32)
// EPI 4: float C += relu(acc+bias); half C2 = new value
#define LDH  40                         // halfs per smem row (80B, 16B aligned)
#define STH  (128*LDH)                  // halfs per tile-stage
#define NSTG 4
#define SMEM_MMA (NSTG*2*STH*2)         // 81920 bytes

template<int AMODE>
__device__ __forceinline__ void issue_tile(
    const __half* __restrict__ A, const __half* __restrict__ B,
    uint32_t smA, uint32_t smB, int kc, long long m0, int n0, int lda, int ldbK, int tid)
{
    const int row = tid >> 1;
    const int s0  = (tid & 1) * 2;
#pragma unroll
    for (int j = 0; j < 2; j++) {
        const int slot = s0 + j;                    // 16B = 8 halves
        const uint32_t da = smA + (uint32_t)(row * LDH + slot * 8) * 2u;
        if (AMODE == 0) {
            cpa16(da, A + (m0 + row) * (long long)lda + kc * 32 + slot * 8, true);
        } else {
            const long long grow = m0 + row;
            const int bt = (int)(grow >> 14);
            const int p  = (int)(grow & 16383);
            const int hh = p >> 7, ww = p & 127;
            const int k  = kc * 32 + slot * 8;
            const int r3 = k >> 8, ci = k & 255;
            const int q3 = r3 / 3;
            const int h2 = hh + q3 - 1, w2 = ww + (r3 - q3 * 3) - 1;
            const bool ok = ((unsigned)h2 < 128u) && ((unsigned)w2 < 128u);
            cpa16(da, A + ((((long long)bt << 7) + h2) * 128 + w2) * 256 + ci, ok);
        }
        const uint32_t db = smB + (uint32_t)(row * LDH + slot * 8) * 2u;
        cpa16(db, B + (long long)(n0 + row) * ldbK + kc * 32 + slot * 8, true);
    }
}

template<int AMODE, int EPI>
__global__ void __launch_bounds__(256, 2) k_mma(
    const __half* __restrict__ A, const __half* __restrict__ B,
    const float* __restrict__ bias, void* __restrict__ Cv,
    __half* __restrict__ C2, const float* __restrict__ up,
    int K, int lda, int ldc)
{
    extern __shared__ __half smh[];
    const uint32_t smbase = smem_u32(smh);

    const int tid  = threadIdx.x;
    const int lane = tid & 31;
    const int wid  = tid >> 5;
    const int wm   = wid >> 1;          // 0..3
    const int wn   = wid & 1;           // 0..1
    const int gq   = lane >> 2;         // groupID 0..7
    const int tg   = lane & 3;          // thread-in-group
    const long long m0 = (long long)blockIdx.y * 128;
    const int n0 = blockIdx.x * 128;
    const int NC = K >> 5;

#pragma unroll
    for (int s = 0; s < NSTG; s++) {
        if (s < NC) {
            issue_tile<AMODE>(A, B, smbase + (uint32_t)(s*2*STH)*2u,
                              smbase + (uint32_t)((s*2+1)*STH)*2u, s, m0, n0, lda, K, tid);
            CPA_COMMIT();
        }
    }

    float acc[2][8][4];
#pragma unroll
    for (int i = 0; i < 2; i++)
#pragma unroll
        for (int j = 0; j < 8; j++)
#pragma unroll
            for (int t = 0; t < 4; t++) acc[i][j][t] = 0.f;

    for (int kc = 0; kc < NC; kc++) {
        const int st = kc % NSTG;
        const int rem = NC - 1 - kc;
        if (rem >= 3)      CPA_WAIT(3);
        else if (rem == 2) CPA_WAIT(2);
        else if (rem == 1) CPA_WAIT(1);
        else               CPA_WAIT(0);
        __syncthreads();

        const __half* bufA = smh + st * 2 * STH;
        const __half* bufB = bufA + STH;
#pragma unroll
        for (int ks = 0; ks < 2; ks++) {
            const int kb = ks * 16 + tg * 2;
            uint32_t afr[2][4], bfr[8][2];
#pragma unroll
            for (int im = 0; im < 2; im++) {
                const int rr = wm * 32 + im * 16 + gq;
                afr[im][0] = *(const uint32_t*)&bufA[ rr      * LDH + kb    ];
                afr[im][1] = *(const uint32_t*)&bufA[(rr + 8) * LDH + kb    ];
                afr[im][2] = *(const uint32_t*)&bufA[ rr      * LDH + kb + 8];
                afr[im][3] = *(const uint32_t*)&bufA[(rr + 8) * LDH + kb + 8];
            }
#pragma unroll
            for (int in_ = 0; in_ < 8; in_++) {
                const int cb = wn * 64 + in_ * 8 + gq;
                bfr[in_][0] = *(const uint32_t*)&bufB[cb * LDH + kb    ];
                bfr[in_][1] = *(const uint32_t*)&bufB[cb * LDH + kb + 8];
            }
#pragma unroll
            for (int im = 0; im < 2; im++)
#pragma unroll
                for (int in_ = 0; in_ < 8; in_++)
                    mma_f16(acc[im][in_], afr[im], bfr[in_]);
        }
        __syncthreads();
        if (kc + NSTG < NC) {
            issue_tile<AMODE>(A, B, smbase + (uint32_t)(st*2*STH)*2u,
                              smbase + (uint32_t)((st*2+1)*STH)*2u, kc + NSTG, m0, n0, lda, K, tid);
            CPA_COMMIT();
        }
    }

    // ---- epilogue ----
    float* Cf = (float*)Cv;
    __half* Ch = (__half*)Cv;
#pragma unroll
    for (int im = 0; im < 2; im++) {
        const long long rbase = m0 + wm * 32 + im * 16 + gq;
#pragma unroll
        for (int half_ = 0; half_ < 2; half_++) {
            const long long r = rbase + half_ * 8;
            float fx = 0.f, fy = 0.f;
            const float* ub = nullptr;
            int x0 = 0, x1 = 0, y0 = 0, y1 = 0;
            if (EPI == 3) {
                const int bt = (int)(r >> 14);
                const int p  = (int)(r & 16383);
                const int w = p & 127, h = p >> 7;
                float sx = fminf(fmaxf(w * 0.5f - 0.25f, 0.f), 63.f);
                float sy = fminf(fmaxf(h * 0.5f - 0.25f, 0.f), 63.f);
                x0 = (int)sx; y0 = (int)sy;
                x1 = min(x0 + 1, 63); y1 = min(y0 + 1, 63);
                fx = sx - x0; fy = sy - y0;
                ub = up + ((long long)bt * LQQ + 1280) * 256;
            }
#pragma unroll
            for (int in_ = 0; in_ < 8; in_++) {
                const int col = n0 + wn * 64 + in_ * 8 + tg * 2;
                float ox = acc[im][in_][half_ * 2 + 0] + bias[col];
                float oy = acc[im][in_][half_ * 2 + 1] + bias[col + 1];
                if (EPI == 1 || EPI == 4) { ox = fmaxf(ox, 0.f); oy = fmaxf(oy, 0.f); }
                if (EPI == 3) {
                    const float w00 = (1.f - fx) * (1.f - fy), w01 = fx * (1.f - fy);
                    const float w10 = (1.f - fx) * fy,         w11 = fx * fy;
                    const float* p00 = ub + (y0 * 64 + x0) * 256 + col;
                    const float* p01 = ub + (y0 * 64 + x1) * 256 + col;
                    const float* p10 = ub + (y1 * 64 + x0) * 256 + col;
                    const float* p11 = ub + (y1 * 64 + x1) * 256 + col;
                    ox += w00 * p00[0] + w01 * p01[0] + w10 * p10[0] + w11 * p11[0];
                    oy += w00 * p00[1] + w01 * p01[1] + w10 * p10[1] + w11 * p11[1];
                }
                const long long ci = r * (long long)ldc + col;
                if (EPI == 0) {
                    *(float2*)(Cf + ci) = make_float2(ox, oy);
                } else if (EPI == 4) {
                    float2 pv = *(float2*)(Cf + ci);
                    float nx = pv.x + ox, ny = pv.y + oy;
                    *(float2*)(Cf + ci) = make_float2(nx, ny);
                    *(__half2*)(C2 + ci) = __floats2half2_rn(nx, ny);
                } else {
                    *(__half2*)(Ch + ci) = __floats2half2_rn(ox, oy);
                }
            }
        }
    }
}

// ---------------- token build: outp(fp32), outh, posf, qh ----------------
__global__ __launch_bounds__(256) void k_build(
    const float* __restrict__ s0, const float* __restrict__ s1, const float* __restrict__ s2,
    const float* __restrict__ p0, const float* __restrict__ p1, const float* __restrict__ p2,
    const float* __restrict__ lev, float* __restrict__ out, __half* __restrict__ outh,
    float* __restrict__ posf, __half* __restrict__ qh)
{
    long long i = (long long)blockIdx.x * 256 + threadIdx.x;
    int c = (int)(i & 255);
    long long r = i >> 8;
    int q  = (int)(r % LQQ);
    int bt = (int)(r / LQQ);
    int l, H, qq;
    if (q < 256)       { l = 0; H = 16; qq = q; }
    else if (q < 1280) { l = 1; H = 32; qq = q - 256; }
    else               { l = 2; H = 64; qq = q - 1280; }
    const float* s = (l == 0) ? s0 : (l == 1 ? s1 : s2);
    const float* p = (l == 0) ? p0 : (l == 1 ? p1 : p2);
    long long src = ((long long)(bt * CC + c)) * H * H + qq;
    float sv = s[src];
    float pv = p[src] + lev[l * CC + c];
    out[i]  = sv;
    outh[i] = __float2half_rn(sv);
    posf[i] = pv;
    qh[i]   = __float2half_rn(sv + pv);
}

// ---------------- deformable sampling: v half, off/aw fp32, out half ----------------
__global__ __launch_bounds__(256) void k_sample(
    const __half* __restrict__ v, const float* __restrict__ off,
    const float* __restrict__ aw, __half* __restrict__ acc)
{
    int bq   = blockIdx.x;
    int h    = threadIdx.x >> 5;
    int lane = threadIdx.x & 31;
    int bt = bq / LQQ, q = bq % LQQ;

    int Hq, qq;
    if (q < 256)       { Hq = 16; qq = q; }
    else if (q < 1280) { Hq = 32; qq = q - 256; }
    else               { Hq = 64; qq = q - 1280; }
    float rx = ((qq % Hq) + 0.5f) / (float)Hq;
    float ry = ((qq / Hq) + 0.5f) / (float)Hq;

    const float* awp = aw + (long long)bq * 128 + h * 12;
    float a[12];
    float m = -1e30f;
#pragma unroll
    for (int j = 0; j < 12; j++) { a[j] = awp[j]; m = fmaxf(m, a[j]); }
    float s = 0.f;
#pragma unroll
    for (int j = 0; j < 12; j++) { a[j] = __expf(a[j] - m); s += a[j]; }
    float inv = 1.f / s;

    const float* offp = off + (long long)bq * 256 + h * 24;
    float sum = 0.f;
    const int starts[3] = {0, 256, 1280};
    const int hs[3]     = {16, 32, 64};

#pragma unroll
    for (int l = 0; l < 3; l++) {
        int H = hs[l], W = hs[l];
        const __half* vl = v + ((long long)bt * LQQ + starts[l]) * CC + h * 32 + lane;
#pragma unroll
        for (int p = 0; p < 4; p++) {
            float ox = offp[(l * 4 + p) * 2 + 0];
            float oy = offp[(l * 4 + p) * 2 + 1];
            float x = rx * W + ox - 0.5f;
            float y = ry * H + oy - 0.5f;
            float x0f = floorf(x), y0f = floorf(y);
            int x0 = (int)x0f, y0 = (int)y0f;
            float fx = x - x0f, fy = y - y0f;
            float w00 = (1.f - fx) * (1.f - fy);
            float w01 = fx * (1.f - fy);
            float w10 = (1.f - fx) * fy;
            float w11 = fx * fy;
            float g = 0.f;
            if (y0 >= 0 && y0 < H) {
                if (x0 >= 0 && x0 < W)         g += w00 * __half2float(vl[(long long)(y0 * W + x0) * CC]);
                if (x0 + 1 >= 0 && x0 + 1 < W) g += w01 * __half2float(vl[(long long)(y0 * W + x0 + 1) * CC]);
            }
            if (y0 + 1 >= 0 && y0 + 1 < H) {
                if (x0 >= 0 && x0 < W)         g += w10 * __half2float(vl[(long long)((y0 + 1) * W + x0) * CC]);
                if (x0 + 1 >= 0 && x0 + 1 < W) g += w11 * __half2float(vl[(long long)((y0 + 1) * W + x0 + 1) * CC]);
            }
            sum += (a[l * 4 + p] * inv) * g;
        }
    }
    acc[(long long)bq * CC + h * 32 + lane] = __float2half_rn(sum);
}

// ---------------- layernorm: out fp32 + outh; optional qh = h(out+posf) -------------
template<int QOUT>
__global__ __launch_bounds__(256) void k_ln(
    const float* __restrict__ res, const float* __restrict__ delta,
    const float* __restrict__ g, const float* __restrict__ b,
    float* __restrict__ out, __half* __restrict__ outh,
    const float* __restrict__ posf, __half* __restrict__ qh)
{
    int row = blockIdx.x, c = threadIdx.x;
    long long idx = (long long)row * CC + c;
    float x = res[idx] + delta[idx];
    float s1 = x, s2 = x * x;
#pragma unroll
    for (int o = 16; o; o >>= 1) {
        s1 += __shfl_xor_sync(0xffffffffu, s1, o);
        s2 += __shfl_xor_sync(0xffffffffu, s2, o);
    }
    __shared__ float a1[8], a2[8];
    int wid = c >> 5, ln = c & 31;
    if (ln == 0) { a1[wid] = s1; a2[wid] = s2; }
    __syncthreads();
    float S1 = 0.f, S2 = 0.f;
#pragma unroll
    for (int k = 0; k < 8; k++) { S1 += a1[k]; S2 += a2[k]; }
    float mean = S1 * (1.f / 256.f);
    float var  = S2 * (1.f / 256.f) - mean * mean;
    float r = rsqrtf(var + 1e-5f);
    float y = (x - mean) * r * g[c] + b[c];
    out[idx]  = y;
    outh[idx] = __float2half_rn(y);
    if (QOUT) qh[idx] = __float2half_rn(y + posf[idx]);
}

// ---------------- mask (B,C,T,H,W) -> token fp32+half; and token->mask ----------------
__global__ __launch_bounds__(256) void k_trpix0(const float* __restrict__ src,
                                                float* __restrict__ dst, __half* __restrict__ dsth)
{
    __shared__ float t[32][33];
    int tx = threadIdx.x & 31, ty = threadIdx.x >> 5;
    int p0 = blockIdx.x << 5;
    int c0 = blockIdx.y << 5;
    int bt = blockIdx.z;
    int b = bt >> 1, tt = bt & 1;
#pragma unroll
    for (int r = 0; r < 4; r++) {
        int c = c0 + ty + r * 8;
        t[ty + r * 8][tx] = src[(((long long)(b * CC + c)) * 2 + tt) * NPIX + p0 + tx];
    }
    __syncthreads();
#pragma unroll
    for (int r = 0; r < 4; r++) {
        int p = p0 + ty + r * 8;
        float v = t[tx][ty + r * 8];
        long long di = ((long long)bt * NPIX + p) * CC + c0 + tx;
        dst[di]  = v;
        dsth[di] = __float2half_rn(v);
    }
}

__global__ __launch_bounds__(256) void k_trpix1(const float* __restrict__ src, float* __restrict__ dst)
{
    __shared__ float t[32][33];
    int tx = threadIdx.x & 31, ty = threadIdx.x >> 5;
    int p0 = blockIdx.x << 5;
    int c0 = blockIdx.y << 5;
    int bt = blockIdx.z;
    int b = bt >> 1, tt = bt & 1;
#pragma unroll
    for (int r = 0; r < 4; r++) {
        int p = p0 + ty + r * 8;
        t[ty + r * 8][tx] = src[((long long)bt * NPIX + p) * CC + c0 + tx];
    }
    __syncthreads();
#pragma unroll
    for (int r = 0; r < 4; r++) {
        int c = c0 + ty + r * 8;
        dst[(((long long)(b * CC + c)) * 2 + tt) * NPIX + p0 + tx] = t[tx][ty + r * 8];
    }
}

// ---------------- weight prep ----------------
// transpose: dst[l][n][k] = h(src[l][k][n]) with N padding
__global__ __launch_bounds__(256) void k_trw(const float* __restrict__ src, __half* __restrict__ dst,
                                             int K, int Nsrc, int Npad)
{
    int l = blockIdx.y;
    long long i = (long long)blockIdx.x * 256 + threadIdx.x;
    int k = (int)(i % K);
    int n = (int)(i / K);
    dst[(long long)l * Npad * K + i] = (n < Nsrc)
        ? __float2half_rn(src[(long long)l * K * Nsrc + (long long)k * Nsrc + n]) : __float2half_rn(0.f);
}
// straight convert (already NxK): lat weights
__global__ __launch_bounds__(256) void k_cvw(const float* __restrict__ src, __half* __restrict__ dst)
{
    long long i = (long long)blockIdx.x * 256 + threadIdx.x;
    dst[i] = __float2half_rn(src[i]);
}
// conv weights: dst[l][o][r*256+ci] = h(w[l][o][ci][r])
__global__ __launch_bounds__(256) void k_trcv(const float* __restrict__ w, __half* __restrict__ dst)
{
    int l = blockIdx.y;
    long long i = (long long)blockIdx.x * 256 + threadIdx.x;   // 256*2304 per layer
    int kk = (int)(i % KCONV);
    int o  = (int)(i / KCONV);
    int r  = kk >> 8, ci = kk & 255;
    dst[(long long)l * CC * KCONV + i] = __float2half_rn(w[(((long long)l * CC + o) * CC + ci) * 9 + r]);
}
__global__ __launch_bounds__(256) void k_padb(const float* __restrict__ src, float* __restrict__ dst,
                                              int Nsrc, int Npad)
{
    int l = blockIdx.y;
    int i = blockIdx.x * 256 + threadIdx.x;
    if (i < Npad) dst[l * Npad + i] = (i < Nsrc) ? src[l * Nsrc + i] : 0.f;
}

// ---------------- host launcher ----------------
extern "C" void kernel_launch(void* const* d_in, const int* in_sizes, int n_in,
                              void* d_out, int out_size)
{
    const float *src0, *src1, *src2, *pos0, *pos1, *pos2;
    if (in_sizes[1] == in_sizes[0]) {
        src0 = (const float*)d_in[0]; pos0 = (const float*)d_in[1];
        src1 = (const float*)d_in[2]; pos1 = (const float*)d_in[3];
        src2 = (const float*)d_in[4]; pos2 = (const float*)d_in[5];
    } else {
        src0 = (const float*)d_in[0]; src1 = (const float*)d_in[1]; src2 = (const float*)d_in[2];
        pos0 = (const float*)d_in[3]; pos1 = (const float*)d_in[4]; pos2 = (const float*)d_in[5];
    }
    const float* mf     = (const float*)d_in[6];
    const float* lev    = (const float*)d_in[7];
    const float* off_w  = (const float*)d_in[8];
    const float* off_b  = (const float*)d_in[9];
    const float* aw_w   = (const float*)d_in[10];
    const float* aw_b   = (const float*)d_in[11];
    const float* val_w  = (const float*)d_in[12];
    const float* val_b  = (const float*)d_in[13];
    const float* out_w  = (const float*)d_in[14];
    const float* out_b  = (const float*)d_in[15];
    const float* ln1_g  = (const float*)d_in[16];
    const float* ln1_b  = (const float*)d_in[17];
    const float* ff1_w  = (const float*)d_in[18];
    const float* ff1_b  = (const float*)d_in[19];
    const float* ff2_w  = (const float*)d_in[20];
    const float* ff2_b  = (const float*)d_in[21];
    const float* ln2_g  = (const float*)d_in[22];
    const float* ln2_b  = (const float*)d_in[23];
    const float* lat_w  = (const float*)d_in[24];
    const float* lat_b  = (const float*)d_in[25];
    const float* outc_w = (const float*)d_in[26];
    const float* outc_b = (const float*)d_in[27];

    float* outp = (float*)d_out;
    float* mask = outp + (size_t)ROWS_TOK * CC;

    cudaFuncSetAttribute(k_mma<0,0>, cudaFuncAttributeMaxDynamicSharedMemorySize, SMEM_MMA);
    cudaFuncSetAttribute(k_mma<0,1>, cudaFuncAttributeMaxDynamicSharedMemorySize, SMEM_MMA);
    cudaFuncSetAttribute(k_mma<0,2>, cudaFuncAttributeMaxDynamicSharedMemorySize, SMEM_MMA);
    cudaFuncSetAttribute(k_mma<0,3>, cudaFuncAttributeMaxDynamicSharedMemorySize, SMEM_MMA);
    cudaFuncSetAttribute(k_mma<1,4>, cudaFuncAttributeMaxDynamicSharedMemorySize, SMEM_MMA);

    float *posf, *offb, *awb, *tmpb, *mtok, *offbp, *awbp;
    __half *outh, *qh, *vh, *acch, *ffh, *xh, *mh;
    __half *valT, *offT, *awT, *outT, *ff1T, *ff2T, *cvT, *latT;
    cudaGetSymbolAddress((void**)&posf, g_posf);
    cudaGetSymbolAddress((void**)&offb, g_off);
    cudaGetSymbolAddress((void**)&awb,  g_aw);
    cudaGetSymbolAddress((void**)&tmpb, g_tmp);
    cudaGetSymbolAddress((void**)&mtok, g_mtok);
    cudaGetSymbolAddress((void**)&outh, g_outh);
    cudaGetSymbolAddress((void**)&qh,   g_qh);
    cudaGetSymbolAddress((void**)&vh,   g_vh);
    cudaGetSymbolAddress((void**)&acch, g_acch);
    cudaGetSymbolAddress((void**)&ffh,  g_ffh);
    cudaGetSymbolAddress((void**)&xh,   g_xh);
    cudaGetSymbolAddress((void**)&mh,   g_mh);
    cudaGetSymbolAddress((void**)&valT, g_valT);
    cudaGetSymbolAddress((void**)&offT, g_offT);
    cudaGetSymbolAddress((void**)&awT,  g_awT);
    cudaGetSymbolAddress((void**)&outT, g_outT);
    cudaGetSymbolAddress((void**)&ff1T, g_ff1T);
    cudaGetSymbolAddress((void**)&ff2T, g_ff2T);
    cudaGetSymbolAddress((void**)&cvT,  g_cvT);
    cudaGetSymbolAddress((void**)&latT, g_latT);
    cudaGetSymbolAddress((void**)&offbp,g_offb);
    cudaGetSymbolAddress((void**)&awbp, g_awb);

    // ---- prologue ----
    k_build<<<ROWS_TOK, 256>>>(src0, src1, src2, pos0, pos1, pos2, lev, outp, outh, posf, qh);
    k_trpix0<<<dim3(512, 8, 4), 256>>>(mf, mtok, mh);
    k_trw<<<dim3(65536/256,  NLAYERS), 256>>>(val_w, valT, 256, 256, 256);
    k_trw<<<dim3(65536/256,  NLAYERS), 256>>>(off_w, offT, 256, 192, 256);
    k_trw<<<dim3(32768/256,  NLAYERS), 256>>>(aw_w,  awT,  256,  96, 128);
    k_trw<<<dim3(65536/256,  NLAYERS), 256>>>(out_w, outT, 256, 256, 256);
    k_trw<<<dim3(262144/256, NLAYERS), 256>>>(ff1_w, ff1T, 256, 1024, 1024);
    k_trw<<<dim3(262144/256, NLAYERS), 256>>>(ff2_w, ff2T, 1024, 256, 256);
    k_trcv<<<dim3(589824/256, NLAYERS), 256>>>(outc_w, cvT);
    k_cvw<<<NLAYERS*65536/256, 256>>>(lat_w, latT);
    k_padb<<<dim3(1, NLAYERS), 256>>>(off_b, offbp, 192, 256);
    k_padb<<<dim3(1, NLAYERS), 256>>>(aw_b,  awbp,   96, 128);

    const int MT = ROWS_TOK / 128;   // 168
    const int MP = ROWS_PIX / 128;   // 512

    for (int i = 0; i < NLAYERS; i++) {
        // qh holds h(outp + posf)
        k_mma<0,2><<<dim3(2, MT), 256, SMEM_MMA>>>(outh, valT + (long long)i*65536,  val_b + i*256, vh,   nullptr, nullptr, 256, 256, 256);
        k_mma<0,0><<<dim3(2, MT), 256, SMEM_MMA>>>(qh,   offT + (long long)i*65536,  offbp + i*256, offb, nullptr, nullptr, 256, 256, 256);
        k_mma<0,0><<<dim3(1, MT), 256, SMEM_MMA>>>(qh,   awT  + (long long)i*32768,  awbp  + i*128, awb,  nullptr, nullptr, 256, 256, 128);

        k_sample<<<ROWS_TOK, 256>>>(vh, offb, awb, acch);

        k_mma<0,0><<<dim3(2, MT), 256, SMEM_MMA>>>(acch, outT + (long long)i*65536,  out_b + i*256, tmpb, nullptr, nullptr, 256, 256, 256);
        k_ln<0><<<ROWS_TOK, 256>>>(outp, tmpb, ln1_g + i*256, ln1_b + i*256, outp, outh, nullptr, nullptr);

        k_mma<0,1><<<dim3(8, MT), 256, SMEM_MMA>>>(outh, ff1T + (long long)i*262144, ff1_b + i*1024, ffh, nullptr, nullptr, 256, 256, 1024);
        k_mma<0,0><<<dim3(2, MT), 256, SMEM_MMA>>>(ffh,  ff2T + (long long)i*262144, ff2_b + i*256, tmpb, nullptr, nullptr, 1024, 1024, 256);
        k_ln<1><<<ROWS_TOK, 256>>>(outp, tmpb, ln2_g + i*256, ln2_b + i*256, outp, outh, posf, qh);

        // FPN: xh = h(lat(mh)+bias+upsample(outp)); mtok += relu(conv3x3(xh)+b), mh = h(mtok)
        k_mma<0,3><<<dim3(2, MP), 256, SMEM_MMA>>>(mh, latT + (long long)i*65536, lat_b + i*256, xh, nullptr, outp, 256, 256, 256);
        k_mma<1,4><<<dim3(2, MP), 256, SMEM_MMA>>>(xh, cvT + (long long)i*589824, outc_b + i*256, mtok, mh, nullptr, KCONV, 0, 256);
    }

    // ---- epilogue: mask tokens back to (B,C,T,H,W) ----
    k_trpix1<<<dim3(512, 8, 4), 256>>>(mtok, mask);
}

// round 6
// speedup vs baseline: 4.4090x; 1.0222x over previous
#include <cuda_runtime.h>
#include <cuda_fp16.h>
#include <cstdint>
#include <math.h>

// ---------------- problem constants ----------------
#define CC        256
#define LQQ       5376
#define BTT       4
#define NLAYERS   6
#define NPIX      16384
#define ROWS_TOK  (BTT*LQQ)     // 21504 = 168*128
#define ROWS_PIX  (BTT*NPIX)    // 65536 = 512*128
#define KCONV     2304

// ---------------- scratch (device globals) ----------------
__device__ float  g_posf[ROWS_TOK*CC];
__device__ float  g_oa  [ROWS_TOK*384];                // off(0..191 @0) + aw(0..95 @256), stride 384
__device__ float  g_tmp [ROWS_TOK*CC];
__device__ float  g_mtok[(long long)ROWS_PIX*CC];      // fp32 mask master (token layout)
__device__ __half g_outh[ROWS_TOK*CC];
__device__ __half g_qh  [ROWS_TOK*CC];
__device__ __half g_vh  [ROWS_TOK*CC];
__device__ __half g_acch[ROWS_TOK*CC];
__device__ __half g_ffh [ROWS_TOK*1024];
__device__ __half g_xh  [(long long)ROWS_PIX*CC];      // conv input (half)
__device__ __half g_mh  [(long long)ROWS_PIX*CC];      // mask half shadow (lat A input)
__device__ __half g_valT[NLAYERS*65536];
__device__ __half g_oaT [NLAYERS*98304];               // combined off+aw weights [384][256]
__device__ __half g_outT[NLAYERS*65536];
__device__ __half g_ff1T[NLAYERS*262144];
__device__ __half g_ff2T[NLAYERS*262144];
__device__ __half g_cvT [NLAYERS*589824];
__device__ __half g_latT[NLAYERS*65536];
__device__ float  g_oab [NLAYERS*384];                 // combined off+aw bias

// ---------------- helpers ----------------
__device__ __forceinline__ void mma_f16(float* d, const uint32_t* a, const uint32_t* b){
    asm volatile("mma.sync.aligned.m16n8k16.row.col.f32.f16.f16.f32 "
        "{%0,%1,%2,%3}, {%4,%5,%6,%7}, {%8,%9}, {%0,%1,%2,%3};"
        : "+f"(d[0]), "+f"(d[1]), "+f"(d[2]), "+f"(d[3])
        : "r"(a[0]), "r"(a[1]), "r"(a[2]), "r"(a[3]), "r"(b[0]), "r"(b[1]));
}
__device__ __forceinline__ void ldsm4(uint32_t* r, uint32_t addr){
    asm volatile("ldmatrix.sync.aligned.m8n8.x4.shared.b16 {%0,%1,%2,%3}, [%4];"
        : "=r"(r[0]), "=r"(r[1]), "=r"(r[2]), "=r"(r[3]) : "r"(addr));
}
__device__ __forceinline__ uint32_t smem_u32(const void* p){
    uint32_t a; asm("{ .reg .u64 t; cvta.to.shared.u64 t, %1; cvt.u32.u64 %0, t; }" : "=r"(a) : "l"(p)); return a;
}
__device__ __forceinline__ void cpa16(uint32_t dst, const void* src, bool ok){
    int sz = ok ? 16 : 0;
    asm volatile("cp.async.cg.shared.global [%0], [%1], 16, %2;\n"
                 :: "r"(dst), "l"(src), "r"(sz) : "memory");
}
#define CPA_COMMIT() asm volatile("cp.async.commit_group;" ::: "memory")
#define CPA_WAIT(n)  asm volatile("cp.async.wait_group %0;" :: "n"(n) : "memory")

// ---------------- fp16 mma GEMM: C[M,N] = A[M,K] * B^T (B NxK K-major half) + bias ----
// BM=BN=128, BK=32, 256 thr, 8 warps (4x2), warp 32x64. 4-stage cp.async. ldmatrix frags.
// AMODE 0: A row-major half (lda). AMODE 1: conv3x3 gather from xh (bt,128,128,256 half).
// EPI 0: float C = acc+bias
// EPI 1: half  C = relu(acc+bias)
// EPI 2: half  C = acc+bias
// EPI 3: half  C = acc+bias+bilinear_up(up fp32)
// EPI 4: float C += relu(acc+bias); half C2 = new value
#define LDH  40                         // halfs per smem row (80B, 16B aligned)
#define STH  (128*LDH)                  // halfs per tile-stage
#define NSTG 4
#define SMEM_MMA (NSTG*2*STH*2)         // 81920 bytes

template<int AMODE>
__device__ __forceinline__ void issue_tile(
    const __half* __restrict__ A, const __half* __restrict__ B,
    uint32_t smA, uint32_t smB, int kc, long long m0, int n0, int lda, int ldbK, int tid)
{
    const int row = tid >> 1;
    const int s0  = (tid & 1) * 2;
#pragma unroll
    for (int j = 0; j < 2; j++) {
        const int slot = s0 + j;                    // 16B = 8 halves
        const uint32_t da = smA + (uint32_t)(row * LDH + slot * 8) * 2u;
        if (AMODE == 0) {
            cpa16(da, A + (m0 + row) * (long long)lda + kc * 32 + slot * 8, true);
        } else {
            const long long grow = m0 + row;
            const int bt = (int)(grow >> 14);
            const int p  = (int)(grow & 16383);
            const int hh = p >> 7, ww = p & 127;
            const int k  = kc * 32 + slot * 8;
            const int r3 = k >> 8, ci = k & 255;
            const int q3 = r3 / 3;
            const int h2 = hh + q3 - 1, w2 = ww + (r3 - q3 * 3) - 1;
            const bool ok = ((unsigned)h2 < 128u) && ((unsigned)w2 < 128u);
            cpa16(da, A + ((((long long)bt << 7) + h2) * 128 + w2) * 256 + ci, ok);
        }
        const uint32_t db = smB + (uint32_t)(row * LDH + slot * 8) * 2u;
        cpa16(db, B + (long long)(n0 + row) * ldbK + kc * 32 + slot * 8, true);
    }
}

template<int AMODE, int EPI>
__global__ void __launch_bounds__(256, 2) k_mma(
    const __half* __restrict__ A, const __half* __restrict__ B,
    const float* __restrict__ bias, void* __restrict__ Cv,
    __half* __restrict__ C2, const float* __restrict__ up,
    int K, int lda, int ldc)
{
    extern __shared__ __half smh[];
    const uint32_t smbase = smem_u32(smh);

    const int tid  = threadIdx.x;
    const int lane = tid & 31;
    const int wid  = tid >> 5;
    const int wm   = wid >> 1;          // 0..3
    const int wn   = wid & 1;           // 0..1
    const int gq   = lane >> 2;
    const int tg   = lane & 3;
    const long long m0 = (long long)blockIdx.y * 128;
    const int n0 = blockIdx.x * 128;
    const int NC = K >> 5;

    // per-thread ldmatrix element offsets (in halfs)
    const int aoff = (wm * 32 + (lane & 7) + (lane & 8)) * LDH + ((lane & 16) >> 1);
    const int boff = (wn * 64 + (lane & 7) + ((lane & 16) >> 1)) * LDH + (lane & 8);

#pragma unroll
    for (int s = 0; s < NSTG; s++) {
        if (s < NC) {
            issue_tile<AMODE>(A, B, smbase + (uint32_t)(s*2*STH)*2u,
                              smbase + (uint32_t)((s*2+1)*STH)*2u, s, m0, n0, lda, K, tid);
            CPA_COMMIT();
        }
    }

    float acc[2][8][4];
#pragma unroll
    for (int i = 0; i < 2; i++)
#pragma unroll
        for (int j = 0; j < 8; j++)
#pragma unroll
            for (int t = 0; t < 4; t++) acc[i][j][t] = 0.f;

    for (int kc = 0; kc < NC; kc++) {
        const int st = kc % NSTG;
        const int rem = NC - 1 - kc;
        if (rem >= 3)      CPA_WAIT(3);
        else if (rem == 2) CPA_WAIT(2);
        else if (rem == 1) CPA_WAIT(1);
        else               CPA_WAIT(0);
        __syncthreads();

        const uint32_t stA = smbase + (uint32_t)(st * 2 * STH) * 2u;
        const uint32_t stB = stA + (uint32_t)STH * 2u;
#pragma unroll
        for (int ks = 0; ks < 2; ks++) {
            uint32_t afr[2][4], bfr[8][2];
#pragma unroll
            for (int im = 0; im < 2; im++)
                ldsm4(afr[im], stA + (uint32_t)(aoff + im * 16 * LDH + ks * 16) * 2u);
#pragma unroll
            for (int g = 0; g < 4; g++) {
                uint32_t t4[4];
                ldsm4(t4, stB + (uint32_t)(boff + g * 16 * LDH + ks * 16) * 2u);
                bfr[2*g][0] = t4[0]; bfr[2*g][1] = t4[1];
                bfr[2*g+1][0] = t4[2]; bfr[2*g+1][1] = t4[3];
            }
#pragma unroll
            for (int im = 0; im < 2; im++)
#pragma unroll
                for (int in_ = 0; in_ < 8; in_++)
                    mma_f16(acc[im][in_], afr[im], bfr[in_]);
        }
        __syncthreads();
        if (kc + NSTG < NC) {
            issue_tile<AMODE>(A, B, smbase + (uint32_t)(st*2*STH)*2u,
                              smbase + (uint32_t)((st*2+1)*STH)*2u, kc + NSTG, m0, n0, lda, K, tid);
            CPA_COMMIT();
        }
    }

    // ---- epilogue ----
    float* Cf = (float*)Cv;
    __half* Ch = (__half*)Cv;
#pragma unroll
    for (int im = 0; im < 2; im++) {
        const long long rbase = m0 + wm * 32 + im * 16 + gq;
#pragma unroll
        for (int half_ = 0; half_ < 2; half_++) {
            const long long r = rbase + half_ * 8;
            float fx = 0.f, fy = 0.f;
            const float* ub = nullptr;
            int x0 = 0, x1 = 0, y0 = 0, y1 = 0;
            if (EPI == 3) {
                const int bt = (int)(r >> 14);
                const int p  = (int)(r & 16383);
                const int w = p & 127, h = p >> 7;
                float sx = fminf(fmaxf(w * 0.5f - 0.25f, 0.f), 63.f);
                float sy = fminf(fmaxf(h * 0.5f - 0.25f, 0.f), 63.f);
                x0 = (int)sx; y0 = (int)sy;
                x1 = min(x0 + 1, 63); y1 = min(y0 + 1, 63);
                fx = sx - x0; fy = sy - y0;
                ub = up + ((long long)bt * LQQ + 1280) * 256;
            }
#pragma unroll
            for (int in_ = 0; in_ < 8; in_++) {
                const int col = n0 + wn * 64 + in_ * 8 + tg * 2;
                float ox = acc[im][in_][half_ * 2 + 0] + bias[col];
                float oy = acc[im][in_][half_ * 2 + 1] + bias[col + 1];
                if (EPI == 1 || EPI == 4) { ox = fmaxf(ox, 0.f); oy = fmaxf(oy, 0.f); }
                if (EPI == 3) {
                    const float w00 = (1.f - fx) * (1.f - fy), w01 = fx * (1.f - fy);
                    const float w10 = (1.f - fx) * fy,         w11 = fx * fy;
                    const float* p00 = ub + (y0 * 64 + x0) * 256 + col;
                    const float* p01 = ub + (y0 * 64 + x1) * 256 + col;
                    const float* p10 = ub + (y1 * 64 + x0) * 256 + col;
                    const float* p11 = ub + (y1 * 64 + x1) * 256 + col;
                    ox += w00 * p00[0] + w01 * p01[0] + w10 * p10[0] + w11 * p11[0];
                    oy += w00 * p00[1] + w01 * p01[1] + w10 * p10[1] + w11 * p11[1];
                }
                const long long ci = r * (long long)ldc + col;
                if (EPI == 0) {
                    *(float2*)(Cf + ci) = make_float2(ox, oy);
                } else if (EPI == 4) {
                    float2 pv = *(float2*)(Cf + ci);
                    float nx = pv.x + ox, ny = pv.y + oy;
                    *(float2*)(Cf + ci) = make_float2(nx, ny);
                    *(__half2*)(C2 + ci) = __floats2half2_rn(nx, ny);
                } else {
                    *(__half2*)(Ch + ci) = __floats2half2_rn(ox, oy);
                }
            }
        }
    }
}

// ---------------- token build: outp(fp32), outh, posf, qh ----------------
__global__ __launch_bounds__(256) void k_build(
    const float* __restrict__ s0, const float* __restrict__ s1, const float* __restrict__ s2,
    const float* __restrict__ p0, const float* __restrict__ p1, const float* __restrict__ p2,
    const float* __restrict__ lev, float* __restrict__ out, __half* __restrict__ outh,
    float* __restrict__ posf, __half* __restrict__ qh)
{
    long long i = (long long)blockIdx.x * 256 + threadIdx.x;
    int c = (int)(i & 255);
    long long r = i >> 8;
    int q  = (int)(r % LQQ);
    int bt = (int)(r / LQQ);
    int l, H, qq;
    if (q < 256)       { l = 0; H = 16; qq = q; }
    else if (q < 1280) { l = 1; H = 32; qq = q - 256; }
    else               { l = 2; H = 64; qq = q - 1280; }
    const float* s = (l == 0) ? s0 : (l == 1 ? s1 : s2);
    const float* p = (l == 0) ? p0 : (l == 1 ? p1 : p2);
    long long src = ((long long)(bt * CC + c)) * H * H + qq;
    float sv = s[src];
    float pv = p[src] + lev[l * CC + c];
    out[i]  = sv;
    outh[i] = __float2half_rn(sv);
    posf[i] = pv;
    qh[i]   = __float2half_rn(sv + pv);
}

// ---------------- deformable sampling: v half, oa fp32 (stride 384), out half -------
__global__ __launch_bounds__(256) void k_sample(
    const __half* __restrict__ v, const float* __restrict__ oa, __half* __restrict__ acc)
{
    int bq   = blockIdx.x;
    int h    = threadIdx.x >> 5;
    int lane = threadIdx.x & 31;
    int bt = bq / LQQ, q = bq % LQQ;

    int Hq, qq;
    if (q < 256)       { Hq = 16; qq = q; }
    else if (q < 1280) { Hq = 32; qq = q - 256; }
    else               { Hq = 64; qq = q - 1280; }
    float rx = ((qq % Hq) + 0.5f) / (float)Hq;
    float ry = ((qq / Hq) + 0.5f) / (float)Hq;

    const float* awp = oa + (long long)bq * 384 + 256 + h * 12;
    float a[12];
    float m = -1e30f;
#pragma unroll
    for (int j = 0; j < 12; j++) { a[j] = awp[j]; m = fmaxf(m, a[j]); }
    float s = 0.f;
#pragma unroll
    for (int j = 0; j < 12; j++) { a[j] = __expf(a[j] - m); s += a[j]; }
    float inv = 1.f / s;

    const float* offp = oa + (long long)bq * 384 + h * 24;
    float sum = 0.f;
    const int starts[3] = {0, 256, 1280};
    const int hs[3]     = {16, 32, 64};

#pragma unroll
    for (int l = 0; l < 3; l++) {
        int H = hs[l], W = hs[l];
        const __half* vl = v + ((long long)bt * LQQ + starts[l]) * CC + h * 32 + lane;
#pragma unroll
        for (int p = 0; p < 4; p++) {
            float ox = offp[(l * 4 + p) * 2 + 0];
            float oy = offp[(l * 4 + p) * 2 + 1];
            float x = rx * W + ox - 0.5f;
            float y = ry * H + oy - 0.5f;
            float x0f = floorf(x), y0f = floorf(y);
            int x0 = (int)x0f, y0 = (int)y0f;
            float fx = x - x0f, fy = y - y0f;
            float w00 = (1.f - fx) * (1.f - fy);
            float w01 = fx * (1.f - fy);
            float w10 = (1.f - fx) * fy;
            float w11 = fx * fy;
            float g = 0.f;
            if (y0 >= 0 && y0 < H) {
                if (x0 >= 0 && x0 < W)         g += w00 * __half2float(vl[(long long)(y0 * W + x0) * CC]);
                if (x0 + 1 >= 0 && x0 + 1 < W) g += w01 * __half2float(vl[(long long)(y0 * W + x0 + 1) * CC]);
            }
            if (y0 + 1 >= 0 && y0 + 1 < H) {
                if (x0 >= 0 && x0 < W)         g += w10 * __half2float(vl[(long long)((y0 + 1) * W + x0) * CC]);
                if (x0 + 1 >= 0 && x0 + 1 < W) g += w11 * __half2float(vl[(long long)((y0 + 1) * W + x0 + 1) * CC]);
            }
            sum += (a[l * 4 + p] * inv) * g;
        }
    }
    acc[(long long)bq * CC + h * 32 + lane] = __float2half_rn(sum);
}

// ---------------- layernorm: out fp32 + outh; optional qh = h(out+posf) -------------
template<int QOUT>
__global__ __launch_bounds__(256) void k_ln(
    const float* __restrict__ res, const float* __restrict__ delta,
    const float* __restrict__ g, const float* __restrict__ b,
    float* __restrict__ out, __half* __restrict__ outh,
    const float* __restrict__ posf, __half* __restrict__ qh)
{
    int row = blockIdx.x, c = threadIdx.x;
    long long idx = (long long)row * CC + c;
    float x = res[idx] + delta[idx];
    float s1 = x, s2 = x * x;
#pragma unroll
    for (int o = 16; o; o >>= 1) {
        s1 += __shfl_xor_sync(0xffffffffu, s1, o);
        s2 += __shfl_xor_sync(0xffffffffu, s2, o);
    }
    __shared__ float a1[8], a2[8];
    int wid = c >> 5, ln = c & 31;
    if (ln == 0) { a1[wid] = s1; a2[wid] = s2; }
    __syncthreads();
    float S1 = 0.f, S2 = 0.f;
#pragma unroll
    for (int k = 0; k < 8; k++) { S1 += a1[k]; S2 += a2[k]; }
    float mean = S1 * (1.f / 256.f);
    float var  = S2 * (1.f / 256.f) - mean * mean;
    float r = rsqrtf(var + 1e-5f);
    float y = (x - mean) * r * g[c] + b[c];
    out[idx]  = y;
    outh[idx] = __float2half_rn(y);
    if (QOUT) qh[idx] = __float2half_rn(y + posf[idx]);
}

// ---------------- mask (B,C,T,H,W) -> token fp32+half; and token->mask ----------------
__global__ __launch_bounds__(256) void k_trpix0(const float* __restrict__ src,
                                                float* __restrict__ dst, __half* __restrict__ dsth)
{
    __shared__ float t[32][33];
    int tx = threadIdx.x & 31, ty = threadIdx.x >> 5;
    int p0 = blockIdx.x << 5;
    int c0 = blockIdx.y << 5;
    int bt = blockIdx.z;
    int b = bt >> 1, tt = bt & 1;
#pragma unroll
    for (int r = 0; r < 4; r++) {
        int c = c0 + ty + r * 8;
        t[ty + r * 8][tx] = src[(((long long)(b * CC + c)) * 2 + tt) * NPIX + p0 + tx];
    }
    __syncthreads();
#pragma unroll
    for (int r = 0; r < 4; r++) {
        int p = p0 + ty + r * 8;
        float v = t[tx][ty + r * 8];
        long long di = ((long long)bt * NPIX + p) * CC + c0 + tx;
        dst[di]  = v;
        dsth[di] = __float2half_rn(v);
    }
}

__global__ __launch_bounds__(256) void k_trpix1(const float* __restrict__ src, float* __restrict__ dst)
{
    __shared__ float t[32][33];
    int tx = threadIdx.x & 31, ty = threadIdx.x >> 5;
    int p0 = blockIdx.x << 5;
    int c0 = blockIdx.y << 5;
    int bt = blockIdx.z;
    int b = bt >> 1, tt = bt & 1;
#pragma unroll
    for (int r = 0; r < 4; r++) {
        int p = p0 + ty + r * 8;
        t[ty + r * 8][tx] = src[((long long)bt * NPIX + p) * CC + c0 + tx];
    }
    __syncthreads();
#pragma unroll
    for (int r = 0; r < 4; r++) {
        int c = c0 + ty + r * 8;
        dst[(((long long)(b * CC + c)) * 2 + tt) * NPIX + p0 + tx] = t[tx][ty + r * 8];
    }
}

// ---------------- weight prep ----------------
__global__ __launch_bounds__(256) void k_trw(const float* __restrict__ src, __half* __restrict__ dst,
                                             int K, int Nsrc, int Npad)
{
    int l = blockIdx.y;
    long long i = (long long)blockIdx.x * 256 + threadIdx.x;
    int k = (int)(i % K);
    int n = (int)(i / K);
    dst[(long long)l * Npad * K + i] = (n < Nsrc)
        ? __float2half_rn(src[(long long)l * K * Nsrc + (long long)k * Nsrc + n]) : __float2half_rn(0.f);
}
// combined off+aw transpose: dst[l][n][k], n<192: off[k][n]; 256<=n<352: aw[k][n-256]
__global__ __launch_bounds__(256) void k_troa(const float* __restrict__ off_w,
                                              const float* __restrict__ aw_w, __half* __restrict__ dst)
{
    int l = blockIdx.y;
    int i = blockIdx.x * 256 + threadIdx.x;   // 384*256
    int k = i & 255;
    int n = i >> 8;
    float v = 0.f;
    if (n < 192)                 v = off_w[((long long)l * 256 + k) * 192 + n];
    else if (n >= 256 && n < 352) v = aw_w[((long long)l * 256 + k) * 96 + (n - 256)];
    dst[(long long)l * 98304 + i] = __float2half_rn(v);
}
__global__ __launch_bounds__(256) void k_padoa(const float* __restrict__ off_b,
                                               const float* __restrict__ aw_b, float* __restrict__ dst)
{
    int l = blockIdx.y;
    int i = blockIdx.x * 256 + threadIdx.x;
    if (i >= 384) return;
    float v = 0.f;
    if (i < 192)                 v = off_b[l * 192 + i];
    else if (i >= 256 && i < 352) v = aw_b[l * 96 + (i - 256)];
    dst[l * 384 + i] = v;
}
__global__ __launch_bounds__(256) void k_cvw(const float* __restrict__ src, __half* __restrict__ dst)
{
    long long i = (long long)blockIdx.x * 256 + threadIdx.x;
    dst[i] = __float2half_rn(src[i]);
}
__global__ __launch_bounds__(256) void k_trcv(const float* __restrict__ w, __half* __restrict__ dst)
{
    int l = blockIdx.y;
    long long i = (long long)blockIdx.x * 256 + threadIdx.x;   // 256*2304 per layer
    int kk = (int)(i % KCONV);
    int o  = (int)(i / KCONV);
    int r  = kk >> 8, ci = kk & 255;
    dst[(long long)l * CC * KCONV + i] = __float2half_rn(w[(((long long)l * CC + o) * CC + ci) * 9 + r]);
}

// ---------------- host launcher ----------------
extern "C" void kernel_launch(void* const* d_in, const int* in_sizes, int n_in,
                              void* d_out, int out_size)
{
    const float *src0, *src1, *src2, *pos0, *pos1, *pos2;
    if (in_sizes[1] == in_sizes[0]) {
        src0 = (const float*)d_in[0]; pos0 = (const float*)d_in[1];
        src1 = (const float*)d_in[2]; pos1 = (const float*)d_in[3];
        src2 = (const float*)d_in[4]; pos2 = (const float*)d_in[5];
    } else {
        src0 = (const float*)d_in[0]; src1 = (const float*)d_in[1]; src2 = (const float*)d_in[2];
        pos0 = (const float*)d_in[3]; pos1 = (const float*)d_in[4]; pos2 = (const float*)d_in[5];
    }
    const float* mf     = (const float*)d_in[6];
    const float* lev    = (const float*)d_in[7];
    const float* off_w  = (const float*)d_in[8];
    const float* off_b  = (const float*)d_in[9];
    const float* aw_w   = (const float*)d_in[10];
    const float* aw_b   = (const float*)d_in[11];
    const float* val_w  = (const float*)d_in[12];
    const float* val_b  = (const float*)d_in[13];
    const float* out_w  = (const float*)d_in[14];
    const float* out_b  = (const float*)d_in[15];
    const float* ln1_g  = (const float*)d_in[16];
    const float* ln1_b  = (const float*)d_in[17];
    const float* ff1_w  = (const float*)d_in[18];
    const float* ff1_b  = (const float*)d_in[19];
    const float* ff2_w  = (const float*)d_in[20];
    const float* ff2_b  = (const float*)d_in[21];
    const float* ln2_g  = (const float*)d_in[22];
    const float* ln2_b  = (const float*)d_in[23];
    const float* lat_w  = (const float*)d_in[24];
    const float* lat_b  = (const float*)d_in[25];
    const float* outc_w = (const float*)d_in[26];
    const float* outc_b = (const float*)d_in[27];

    float* outp = (float*)d_out;
    float* mask = outp + (size_t)ROWS_TOK * CC;

    cudaFuncSetAttribute(k_mma<0,0>, cudaFuncAttributeMaxDynamicSharedMemorySize, SMEM_MMA);
    cudaFuncSetAttribute(k_mma<0,1>, cudaFuncAttributeMaxDynamicSharedMemorySize, SMEM_MMA);
    cudaFuncSetAttribute(k_mma<0,2>, cudaFuncAttributeMaxDynamicSharedMemorySize, SMEM_MMA);
    cudaFuncSetAttribute(k_mma<0,3>, cudaFuncAttributeMaxDynamicSharedMemorySize, SMEM_MMA);
    cudaFuncSetAttribute(k_mma<1,4>, cudaFuncAttributeMaxDynamicSharedMemorySize, SMEM_MMA);

    float *posf, *oab_buf, *tmpb, *mtok, *oabp;
    __half *outh, *qh, *vh, *acch, *ffh, *xh, *mh;
    __half *valT, *oaT, *outT, *ff1T, *ff2T, *cvT, *latT;
    cudaGetSymbolAddress((void**)&posf, g_posf);
    cudaGetSymbolAddress((void**)&oab_buf, g_oa);
    cudaGetSymbolAddress((void**)&tmpb, g_tmp);
    cudaGetSymbolAddress((void**)&mtok, g_mtok);
    cudaGetSymbolAddress((void**)&outh, g_outh);
    cudaGetSymbolAddress((void**)&qh,   g_qh);
    cudaGetSymbolAddress((void**)&vh,   g_vh);
    cudaGetSymbolAddress((void**)&acch, g_acch);
    cudaGetSymbolAddress((void**)&ffh,  g_ffh);
    cudaGetSymbolAddress((void**)&xh,   g_xh);
    cudaGetSymbolAddress((void**)&mh,   g_mh);
    cudaGetSymbolAddress((void**)&valT, g_valT);
    cudaGetSymbolAddress((void**)&oaT,  g_oaT);
    cudaGetSymbolAddress((void**)&outT, g_outT);
    cudaGetSymbolAddress((void**)&ff1T, g_ff1T);
    cudaGetSymbolAddress((void**)&ff2T, g_ff2T);
    cudaGetSymbolAddress((void**)&cvT,  g_cvT);
    cudaGetSymbolAddress((void**)&latT, g_latT);
    cudaGetSymbolAddress((void**)&oabp, g_oab);

    // ---- prologue ----
    k_build<<<ROWS_TOK, 256>>>(src0, src1, src2, pos0, pos1, pos2, lev, outp, outh, posf, qh);
    k_trpix0<<<dim3(512, 8, 4), 256>>>(mf, mtok, mh);
    k_trw<<<dim3(65536/256,  NLAYERS), 256>>>(val_w, valT, 256, 256, 256);
    k_troa<<<dim3(384, NLAYERS), 256>>>(off_w, aw_w, oaT);
    k_trw<<<dim3(65536/256,  NLAYERS), 256>>>(out_w, outT, 256, 256, 256);
    k_trw<<<dim3(262144/256, NLAYERS), 256>>>(ff1_w, ff1T, 256, 1024, 1024);
    k_trw<<<dim3(262144/256, NLAYERS), 256>>>(ff2_w, ff2T, 1024, 256, 256);
    k_trcv<<<dim3(589824/256, NLAYERS), 256>>>(outc_w, cvT);
    k_cvw<<<NLAYERS*65536/256, 256>>>(lat_w, latT);
    k_padoa<<<dim3(2, NLAYERS), 256>>>(off_b, aw_b, oabp);

    const int MT = ROWS_TOK / 128;   // 168
    const int MP = ROWS_PIX / 128;   // 512

    for (int i = 0; i < NLAYERS; i++) {
        // qh holds h(outp + posf)
        k_mma<0,2><<<dim3(2, MT), 256, SMEM_MMA>>>(outh, valT + (long long)i*65536, val_b + i*256, vh, nullptr, nullptr, 256, 256, 256);
        k_mma<0,0><<<dim3(3, MT), 256, SMEM_MMA>>>(qh,   oaT  + (long long)i*98304, oabp  + i*384, oab_buf, nullptr, nullptr, 256, 256, 384);

        k_sample<<<ROWS_TOK, 256>>>(vh, oab_buf, acch);

        k_mma<0,0><<<dim3(2, MT), 256, SMEM_MMA>>>(acch, outT + (long long)i*65536,  out_b + i*256, tmpb, nullptr, nullptr, 256, 256, 256);
        k_ln<0><<<ROWS_TOK, 256>>>(outp, tmpb, ln1_g + i*256, ln1_b + i*256, outp, outh, nullptr, nullptr);

        k_mma<0,1><<<dim3(8, MT), 256, SMEM_MMA>>>(outh, ff1T + (long long)i*262144, ff1_b + i*1024, ffh, nullptr, nullptr, 256, 256, 1024);
        k_mma<0,0><<<dim3(2, MT), 256, SMEM_MMA>>>(ffh,  ff2T + (long long)i*262144, ff2_b + i*256, tmpb, nullptr, nullptr, 1024, 1024, 256);
        k_ln<1><<<ROWS_TOK, 256>>>(outp, tmpb, ln2_g + i*256, ln2_b + i*256, outp, outh, posf, qh);

        // FPN: xh = h(lat(mh)+bias+upsample(outp)); mtok += relu(conv3x3(xh)+b), mh = h(mtok)
        k_mma<0,3><<<dim3(2, MP), 256, SMEM_MMA>>>(mh, latT + (long long)i*65536, lat_b + i*256, xh, nullptr, outp, 256, 256, 256);
        k_mma<1,4><<<dim3(2, MP), 256, SMEM_MMA>>>(xh, cvT + (long long)i*589824, outc_b + i*256, mtok, mh, nullptr, KCONV, 0, 256);
    }

    // ---- epilogue: mask tokens back to (B,C,T,H,W) ----
    k_trpix1<<<dim3(512, 8, 4), 256>>>(mtok, mask);
}